// round 10
// baseline (speedup 1.0000x reference)
#include <cuda_runtime.h>
#include <cstdint>

#define NN   4096
#define MMm  4096
#define DD   128
#define CC   4
#define NNZ  262144
#define KDIM 512
#define KADD 26214
#define NM   (NN * MMm)
#define CAPC (4u * 1024u * 1024u)
#define DEGC 192                      // per-edge CSR bucket capacity (Poisson(64) tail-safe)
#define RS   768u                     // sample-rank cutoff (1/64 sampling)

// GEMM tiling (mma.sync tf32 path)
#define MT      128
#define NT      128
#define KCH     32
#define NCHUNK  (KDIM / KCH)          // 16
#define LDK     36                    // padded k-stride in floats (32+4)
#define PLANE_F (128 * LDK)           // 4608 floats per plane
#define STAGE_F (4 * PLANE_F)         // 18432 floats per stage
#define SMEM_BYTES (2 * STAGE_F * 4)  // 147456 bytes
#define GT      512                   // gemm threads

// ---------------- scratch (static device memory; no allocs allowed) ----------------
__device__ unsigned  g_ecur[MMm];            // per-edge fill counts
__device__ int       g_eidx[MMm * DEGC];     // bucketed node indices
__device__ float     g_Ahi[NN * KDIM];       // node feature tf32 hi plane
__device__ float     g_Alo[NN * KDIM];       // node feature tf32 lo plane
__device__ float     g_Bhi[MMm * KDIM];      // edge feature tf32 hi plane
__device__ float     g_Blo[MMm * KDIM];      // edge feature tf32 lo plane
__device__ float     g_S[NM];                // similarity matrix (masked)
__device__ unsigned  g_hist[2048];           // SAMPLE histogram
__device__ unsigned  g_cand[CAPC];           // candidate ordered-uints (u >= Bc<<21)
__device__ unsigned  g_candCount;
__device__ unsigned  g_Bc;                   // sample-derived cutoff bucket
__device__ unsigned  g_Tbits;                // exact k-th largest value (ordered bits)

__device__ __forceinline__ unsigned f2ord(float f) {
    unsigned u = __float_as_uint(f);
    return (u & 0x80000000u) ? ~u : (u | 0x80000000u);
}
__device__ __forceinline__ float tf32r(float x) {
    uint32_t o;
    asm("cvt.rna.tf32.f32 %0, %1;" : "=r"(o) : "f"(x));
    return __uint_as_float(o);
}
__device__ __forceinline__ void cpa16(uint32_t dst, const void* src) {
    asm volatile("cp.async.cg.shared.global [%0], [%1], 16;"
                 :: "r"(dst), "l"(__cvta_generic_to_global(src)) : "memory");
}
// m16n8k8 tf32 mma: D = A*B + D  (row.col), fp32 accumulate
__device__ __forceinline__ void mma8(float* c,
                                     uint32_t a0, uint32_t a1, uint32_t a2, uint32_t a3,
                                     uint32_t b0, uint32_t b1) {
    asm volatile(
        "mma.sync.aligned.m16n8k8.row.col.f32.tf32.tf32.f32 "
        "{%0,%1,%2,%3}, {%4,%5,%6,%7}, {%8,%9}, {%0,%1,%2,%3};"
        : "+f"(c[0]), "+f"(c[1]), "+f"(c[2]), "+f"(c[3])
        : "r"(a0), "r"(a1), "r"(a2), "r"(a3), "r"(b0), "r"(b1));
}

// ---------------- K0: zero transient state (runs every replay) ----------------
__global__ void k_zero() {
    int i  = blockIdx.x * blockDim.x + threadIdx.x;
    int st = gridDim.x * blockDim.x;
    for (int j = i; j < MMm;  j += st) g_ecur[j] = 0;
    for (int j = i; j < 2048; j += st) g_hist[j] = 0;
    if (i == 0) g_candCount = 0;
}

// ---------------- K1: bucketed CSR fill (no count/prefix needed) ----------------
__global__ void k_fill(const int* __restrict__ V, const int* __restrict__ E) {
    int i = blockIdx.x * blockDim.x + threadIdx.x;
    if (i < NNZ) {
        int e = E[i];
        unsigned pos = atomicAdd(&g_ecur[e], 1u);
        if (pos < DEGC) g_eidx[e * DEGC + pos] = V[i];
    }
}

// ---------------- K2: build 0.5 * l2norm(x * w_c) features, tf32 hi/lo planes ----------------
// Edge branch gathers node rows via buckets; deterministic fixed-point mean (int64 commutative).
__global__ void k_feat(const float* __restrict__ X, const float* __restrict__ W) {
    int r   = blockIdx.x;
    int isE = blockIdx.y;
    int d   = threadIdx.x;   // 128 threads
    __shared__ float red[128];
    float x;
    if (!isE) {
        x = X[(size_t)r * DD + d];
    } else {
        unsigned deg = g_ecur[r];
        if (deg > DEGC) deg = DEGC;
        const int* lst = g_eidx + r * DEGC;
        long long acc = 0;
        for (unsigned j = 0; j < deg; j++) {
            int v = lst[j];
            acc += __double2ll_rn((double)X[(size_t)v * DD + d] * 4294967296.0);
        }
        float cnt = (float)deg;
        float sum = (float)((double)acc * (1.0 / 4294967296.0));
        x = __fdiv_rn(sum, fmaxf(cnt, 1.0f));
    }
    float* dhi = isE ? g_Bhi : g_Ahi;
    float* dlo = isE ? g_Blo : g_Alo;
#pragma unroll
    for (int c = 0; c < CC; c++) {
        float v = x * W[c * DD + d];
        red[d] = v * v;
        __syncthreads();
        for (int s2 = 64; s2 > 0; s2 >>= 1) {
            if (d < s2) red[d] += red[d + s2];
            __syncthreads();
        }
        float nrm = __fsqrt_rn(red[0]);
        __syncthreads();
        float val = 0.5f * __fdiv_rn(v, fmaxf(nrm, 1e-12f));
        float hi = tf32r(val);
        float lo = tf32r(val - hi);
        dhi[(size_t)r * KDIM + c * DD + d] = hi;
        dlo[(size_t)r * KDIM + c * DD + d] = lo;
    }
}

// ---------------- K3: 3xTF32 mma.sync GEMM  S = A(4096x512) * B(4096x512)^T ----------------
// 128x128 CTA tile, 16 warps (4x4), warp tile 32x32, k-chunk 32, double-buffered cp.async.
__global__ void __launch_bounds__(GT, 1) k_gemm() {
    extern __shared__ __align__(128) float smf[];
    uint32_t sb;
    asm("{ .reg .u64 t; cvta.to.shared.u64 t, %1; cvt.u32.u64 %0, t; }"
        : "=r"(sb) : "l"(smf));
    const int tid = threadIdx.x;
    const int wid = tid >> 5, lane = tid & 31;
    const int g = lane >> 2, t = lane & 3;
    const int wm = wid >> 2, wn = wid & 3;
    const int bm = blockIdx.y * MT, bn = blockIdx.x * NT;

    float acc[2][4][4];
#pragma unroll
    for (int mt = 0; mt < 2; mt++)
#pragma unroll
        for (int nt = 0; nt < 4; nt++)
#pragma unroll
            for (int r = 0; r < 4; r++) acc[mt][nt][r] = 0.0f;

    auto load_chunk = [&](int kt, int stage) {
        uint32_t base = sb + (uint32_t)stage * (STAGE_F * 4);
#pragma unroll
        for (int i = 0; i < 2; i++) {
            int idx = tid + i * GT;
            int row = idx >> 3, c4 = idx & 7;
            uint32_t so = (uint32_t)(row * (LDK * 4) + c4 * 16);
            size_t goA = (size_t)(bm + row) * KDIM + kt * KCH + c4 * 4;
            size_t goB = (size_t)(bn + row) * KDIM + kt * KCH + c4 * 4;
            cpa16(base + so,                  g_Ahi + goA);
            cpa16(base + PLANE_F * 4  + so,   g_Alo + goA);
            cpa16(base + PLANE_F * 8  + so,   g_Bhi + goB);
            cpa16(base + PLANE_F * 12 + so,   g_Blo + goB);
        }
        asm volatile("cp.async.commit_group;" ::: "memory");
    };

    load_chunk(0, 0);

    for (int kt = 0; kt < NCHUNK; kt++) {
        int buf = kt & 1;
        if (kt + 1 < NCHUNK) {
            load_chunk(kt + 1, buf ^ 1);
            asm volatile("cp.async.wait_group 1;" ::: "memory");
        } else {
            asm volatile("cp.async.wait_group 0;" ::: "memory");
        }
        __syncthreads();

        const float* st_ = smf + buf * STAGE_F;
        const float* Ah = st_;
        const float* Al = st_ + PLANE_F;
        const float* Bh = st_ + 2 * PLANE_F;
        const float* Bl = st_ + 3 * PLANE_F;

#pragma unroll
        for (int ks = 0; ks < 4; ks++) {
            const int kb = ks * 8;
            uint32_t bh[4][2], bl[4][2];
#pragma unroll
            for (int nt = 0; nt < 4; nt++) {
                int n0 = wn * 32 + nt * 8 + g;
                int o  = n0 * LDK + kb + t;
                bh[nt][0] = __float_as_uint(Bh[o]);
                bh[nt][1] = __float_as_uint(Bh[o + 4]);
                bl[nt][0] = __float_as_uint(Bl[o]);
                bl[nt][1] = __float_as_uint(Bl[o + 4]);
            }
#pragma unroll
            for (int mt = 0; mt < 2; mt++) {
                int r0 = wm * 32 + mt * 16 + g;
                int o0 = r0 * LDK + kb + t;
                int o1 = (r0 + 8) * LDK + kb + t;
                uint32_t ah0 = __float_as_uint(Ah[o0]);
                uint32_t ah1 = __float_as_uint(Ah[o1]);
                uint32_t ah2 = __float_as_uint(Ah[o0 + 4]);
                uint32_t ah3 = __float_as_uint(Ah[o1 + 4]);
                uint32_t al0 = __float_as_uint(Al[o0]);
                uint32_t al1 = __float_as_uint(Al[o1]);
                uint32_t al2 = __float_as_uint(Al[o0 + 4]);
                uint32_t al3 = __float_as_uint(Al[o1 + 4]);
#pragma unroll
                for (int nt = 0; nt < 4; nt++) {
                    mma8(acc[mt][nt], ah0, ah1, ah2, ah3, bh[nt][0], bh[nt][1]);
                    mma8(acc[mt][nt], ah0, ah1, ah2, ah3, bl[nt][0], bl[nt][1]);
                    mma8(acc[mt][nt], al0, al1, al2, al3, bh[nt][0], bh[nt][1]);
                }
            }
        }
        __syncthreads();
    }

#pragma unroll
    for (int mt = 0; mt < 2; mt++) {
        int r0 = bm + wm * 32 + mt * 16 + g;
#pragma unroll
        for (int nt = 0; nt < 4; nt++) {
            int c = bn + wn * 32 + nt * 8 + 2 * t;
            *(float2*)(g_S + (size_t)r0 * MMm + c)       = make_float2(acc[mt][nt][0], acc[mt][nt][1]);
            *(float2*)(g_S + (size_t)(r0 + 8) * MMm + c) = make_float2(acc[mt][nt][2], acc[mt][nt][3]);
        }
    }
}

// ---------------- K4: mask existing incidences (dedup-safe) ----------------
__global__ void k_mask(const int* __restrict__ V, const int* __restrict__ E) {
    int i = blockIdx.x * blockDim.x + threadIdx.x;
    if (i < NNZ) {
        atomicExch(&g_S[(size_t)V[i] * MMm + E[i]], -1e30f);
    }
}

// ---------------- K5: SAMPLE histogram (1/64 stride, 262144 samples) ----------------
__global__ void k_shist() {
    __shared__ unsigned h[2048];
    for (int j = threadIdx.x; j < 2048; j += blockDim.x) h[j] = 0;
    __syncthreads();
    int i = blockIdx.x * blockDim.x + threadIdx.x;   // 262144 threads
    unsigned u = f2ord(g_S[(size_t)i * 64]);
    atomicAdd(&h[u >> 21], 1u);
    __syncthreads();
    for (int j = threadIdx.x; j < 2048; j += blockDim.x)
        if (h[j]) atomicAdd(&g_hist[j], h[j]);
}

// ---------------- K6: cutoff bucket from sample (largest b with sample-cum >= RS) ----------------
__global__ void k_spick() {
    __shared__ unsigned c[2048];
    int t = threadIdx.x;   // 1024
    c[t] = g_hist[t];
    c[t + 1024] = g_hist[t + 1024];
    __syncthreads();
    for (int off = 1; off < 2048; off <<= 1) {
        unsigned a0 = (t + off < 2048) ? c[t + off] : 0u;
        unsigned a1 = (t + 1024 + off < 2048) ? c[t + 1024 + off] : 0u;
        __syncthreads();
        c[t] += a0; c[t + 1024] += a1;
        __syncthreads();
    }
    for (int b = t; b < 2048; b += 1024) {
        unsigned cum = c[b], nxt = (b + 1 < 2048) ? c[b + 1] : 0u;
        if (cum >= RS && nxt < RS) g_Bc = (unsigned)b;
    }
}

// ---------------- K7: collect all candidates with bucket >= Bc ----------------
__global__ void k_collect() {
    unsigned Bc = g_Bc;
    int i  = blockIdx.x * blockDim.x + threadIdx.x;
    int st = gridDim.x * blockDim.x;
    const float4* S4 = (const float4*)g_S;
    for (int j = i; j < NM / 4; j += st) {
        float4 s = S4[j];
        unsigned u0 = f2ord(s.x), u1 = f2ord(s.y), u2 = f2ord(s.z), u3 = f2ord(s.w);
        if ((u0 >> 21) >= Bc) { unsigned p = atomicAdd(&g_candCount, 1u); if (p < CAPC) g_cand[p] = u0; }
        if ((u1 >> 21) >= Bc) { unsigned p = atomicAdd(&g_candCount, 1u); if (p < CAPC) g_cand[p] = u1; }
        if ((u2 >> 21) >= Bc) { unsigned p = atomicAdd(&g_candCount, 1u); if (p < CAPC) g_cand[p] = u2; }
        if ((u3 >> 21) >= Bc) { unsigned p = atomicAdd(&g_candCount, 1u); if (p < CAPC) g_cand[p] = u3; }
    }
}

// ---------------- K8: exact rank-KADD via 11+11+10 bit refine over candidates (1 block) ----------------
__global__ void k_select() {
    __shared__ unsigned h[2048];
    __shared__ unsigned sB1, sr1, sb2, sr2;
    int t = threadIdx.x;  // 1024
    unsigned nc = g_candCount; if (nc > CAPC) nc = CAPC;

    // level 1: top-11 bits
    h[t] = 0; h[t + 1024] = 0;
    __syncthreads();
    for (unsigned i = t; i < nc; i += 1024)
        atomicAdd(&h[g_cand[i] >> 21], 1u);
    __syncthreads();
    for (int off = 1; off < 2048; off <<= 1) {
        unsigned a0 = (t + off < 2048) ? h[t + off] : 0u;
        unsigned a1 = (t + 1024 + off < 2048) ? h[t + 1024 + off] : 0u;
        __syncthreads();
        h[t] += a0; h[t + 1024] += a1;
        __syncthreads();
    }
    for (int b = t; b < 2048; b += 1024) {
        unsigned cum = h[b], nxt = (b + 1 < 2048) ? h[b + 1] : 0u;
        if (cum >= (unsigned)KADD && nxt < (unsigned)KADD) { sB1 = (unsigned)b; sr1 = (unsigned)KADD - nxt; }
    }
    __syncthreads();
    unsigned B1 = sB1, r1 = sr1;

    // level 2: middle-11 bits within B1
    h[t] = 0; h[t + 1024] = 0;
    __syncthreads();
    for (unsigned i = t; i < nc; i += 1024) {
        unsigned u = g_cand[i];
        if ((u >> 21) == B1) atomicAdd(&h[(u >> 10) & 2047u], 1u);
    }
    __syncthreads();
    for (int off = 1; off < 2048; off <<= 1) {
        unsigned a0 = (t + off < 2048) ? h[t + off] : 0u;
        unsigned a1 = (t + 1024 + off < 2048) ? h[t + 1024 + off] : 0u;
        __syncthreads();
        h[t] += a0; h[t + 1024] += a1;
        __syncthreads();
    }
    for (int b = t; b < 2048; b += 1024) {
        unsigned cum = h[b], nxt = (b + 1 < 2048) ? h[b + 1] : 0u;
        if (cum >= r1 && nxt < r1) { sb2 = (unsigned)b; sr2 = r1 - nxt; }
    }
    __syncthreads();
    unsigned b2 = sb2, r2 = sr2;
    unsigned top21 = (B1 << 11) | b2;

    // level 3: low-10 bits within (B1,b2)
    h[t] = 0;
    __syncthreads();
    for (unsigned i = t; i < nc; i += 1024) {
        unsigned u = g_cand[i];
        if ((u >> 10) == top21) atomicAdd(&h[u & 1023u], 1u);
    }
    __syncthreads();
    for (int off = 1; off < 1024; off <<= 1) {
        unsigned a = (t + off < 1024) ? h[t + off] : 0u;
        __syncthreads();
        h[t] += a;
        __syncthreads();
    }
    unsigned cum = h[t], nxt = (t + 1 < 1024) ? h[t + 1] : 0u;
    if (cum >= r2 && nxt < r2)
        g_Tbits = (B1 << 21) | (b2 << 10) | (unsigned)t;
}

// ---------------- K9: fused output ----------------
__device__ __forceinline__ float outval(float h, float p, float e, float s, unsigned T) {
    float enr = h + ((f2ord(s) >= T) ? 1.0f : 0.0f);
    float pa = __fadd_rn(p, 1e-8f);
    float pb = __fadd_rn(__fsub_rn(1.0f, p), 1e-8f);
    float eb = __fsub_rn(1.0f, e);
    double lhs = (double)e  * (double)pa;
    double rhs = (double)eb * (double)pb;
    return (lhs > rhs) ? enr : 0.0f;
}

__global__ void k_final(const float* __restrict__ H, const float* __restrict__ P,
                        const float* __restrict__ Eps, float* __restrict__ out) {
    unsigned T = g_Tbits;
    int i  = blockIdx.x * blockDim.x + threadIdx.x;
    int st = gridDim.x * blockDim.x;
    const float4* H4 = (const float4*)H;
    const float4* P4 = (const float4*)P;
    const float4* E4 = (const float4*)Eps;
    const float4* S4 = (const float4*)g_S;
    float4* O4 = (float4*)out;
    for (int j = i; j < NM / 4; j += st) {
        float4 h4 = H4[j], p4 = P4[j], e4 = E4[j], s4 = S4[j];
        float4 o;
        o.x = outval(h4.x, p4.x, e4.x, s4.x, T);
        o.y = outval(h4.y, p4.y, e4.y, s4.y, T);
        o.z = outval(h4.z, p4.z, e4.z, s4.z, T);
        o.w = outval(h4.w, p4.w, e4.w, s4.w, T);
        O4[j] = o;
    }
}

// ---------------- launch ----------------
extern "C" void kernel_launch(void* const* d_in, const int* in_sizes, int n_in,
                              void* d_out, int out_size) {
    const float* X   = (const float*)d_in[0];
    const float* H   = (const float*)d_in[1];
    const int*   V   = (const int*)d_in[2];
    const int*   E   = (const int*)d_in[3];
    const float* P   = (const float*)d_in[4];
    const float* W   = (const float*)d_in[5];
    const float* Eps = (const float*)d_in[6];
    float* out = (float*)d_out;

    cudaFuncSetAttribute(k_gemm, cudaFuncAttributeMaxDynamicSharedMemorySize, SMEM_BYTES);

    k_zero<<<64, 256>>>();
    k_fill<<<NNZ / 256, 256>>>(V, E);
    {
        dim3 fg(NN, 2);
        k_feat<<<fg, 128>>>(X, W);
    }
    {
        dim3 gg(MMm / NT, NN / MT);   // (32, 32)
        k_gemm<<<gg, GT, SMEM_BYTES>>>();
    }
    k_mask<<<NNZ / 256, 256>>>(V, E);
    k_shist<<<1024, 256>>>();
    k_spick<<<1, 1024>>>();
    k_collect<<<2048, 256>>>();
    k_select<<<1, 1024>>>();
    k_final<<<4096, 256>>>(H, P, Eps, out);
}

// round 11
// speedup vs baseline: 1.5944x; 1.5944x over previous
#include <cuda_runtime.h>
#include <cuda_fp16.h>
#include <cstdint>

#define NN   4096
#define MMm  4096
#define DD   128
#define CC   4
#define NNZ  262144
#define KDIM 512
#define KADD 26214
#define NM   (NN * MMm)
#define CAPC (4u * 1024u * 1024u)

// GEMM tiling (mma.sync fp16 m16n8k16, 2-term split)
#define MT      128
#define NT      128
#define KCH     32
#define NCHUNK  (KDIM / KCH)          // 16
#define LDKH    40                    // padded k-stride in halves (32+8) -> conflict-free frags
#define PLANE_H (128 * LDKH)          // 5120 halves per plane
#define STAGE_H (4 * PLANE_H)         // 20480 halves per stage
#define SMEM_BYTES (2 * STAGE_H * 2)  // 81920 bytes
#define GT      512                   // gemm threads

// ---------------- scratch (static device memory; no allocs allowed) ----------------
__device__ int       g_cnt[MMm];             // segment counts
__device__ unsigned  g_eoff[MMm + 1];        // CSR offsets
__device__ unsigned  g_ecur[MMm];            // fill cursors
__device__ int       g_eidx[NNZ];            // CSR node indices
__device__ __half    g_Ahi[NN * KDIM];       // node feature fp16 hi plane
__device__ __half    g_Alo[NN * KDIM];       // node feature fp16 lo*2048 plane
__device__ __half    g_Bhi[MMm * KDIM];      // edge feature fp16 hi plane
__device__ __half    g_Blo[MMm * KDIM];      // edge feature fp16 lo*2048 plane
__device__ float     g_S[NM];                // similarity matrix (masked)
__device__ unsigned  g_hist[2048];
__device__ unsigned  g_cand[CAPC];
__device__ unsigned  g_candCount;
__device__ unsigned  g_B1;
__device__ unsigned  g_r1;
__device__ unsigned  g_Tbits;

__device__ __forceinline__ unsigned f2ord(float f) {
    unsigned u = __float_as_uint(f);
    return (u & 0x80000000u) ? ~u : (u | 0x80000000u);
}
__device__ __forceinline__ void cpa16(uint32_t dst, const void* src) {
    asm volatile("cp.async.cg.shared.global [%0], [%1], 16;"
                 :: "r"(dst), "l"(__cvta_generic_to_global(src)) : "memory");
}
// m16n8k16 fp16 mma: D = A*B + D  (row.col), fp32 accumulate
__device__ __forceinline__ void mma16(float* c,
                                      uint32_t a0, uint32_t a1, uint32_t a2, uint32_t a3,
                                      uint32_t b0, uint32_t b1) {
    asm volatile(
        "mma.sync.aligned.m16n8k16.row.col.f32.f16.f16.f32 "
        "{%0,%1,%2,%3}, {%4,%5,%6,%7}, {%8,%9}, {%0,%1,%2,%3};"
        : "+f"(c[0]), "+f"(c[1]), "+f"(c[2]), "+f"(c[3])
        : "r"(a0), "r"(a1), "r"(a2), "r"(a3), "r"(b0), "r"(b1));
}

// ---------------- K0: zero transient state (runs every replay) ----------------
__global__ void k_zero() {
    int i  = blockIdx.x * blockDim.x + threadIdx.x;
    int st = gridDim.x * blockDim.x;
    for (int j = i; j < MMm;  j += st) { g_cnt[j] = 0; g_ecur[j] = 0; }
    for (int j = i; j < 2048; j += st) g_hist[j] = 0;
    if (i == 0) g_candCount = 0;
}

// ---------------- CSR build: count -> prefix -> fill ----------------
__global__ void k_count(const int* __restrict__ E) {
    int i = blockIdx.x * blockDim.x + threadIdx.x;
    if (i < NNZ) atomicAdd(&g_cnt[E[i]], 1);
}

__global__ void k_prefix() {   // exclusive prefix of g_cnt into g_eoff (1 block, 1024 thr)
    __shared__ unsigned s[1024];
    int t = threadIdx.x;
    unsigned c0 = g_cnt[4*t], c1 = g_cnt[4*t+1], c2 = g_cnt[4*t+2], c3 = g_cnt[4*t+3];
    s[t] = c0 + c1 + c2 + c3;
    __syncthreads();
    for (int off = 1; off < 1024; off <<= 1) {
        unsigned v = (t >= off) ? s[t - off] : 0u;
        __syncthreads();
        s[t] += v;
        __syncthreads();
    }
    unsigned base = t ? s[t-1] : 0u;
    g_eoff[4*t]   = base;
    g_eoff[4*t+1] = base + c0;
    g_eoff[4*t+2] = base + c0 + c1;
    g_eoff[4*t+3] = base + c0 + c1 + c2;
    if (t == 1023) g_eoff[MMm] = s[1023];
}

__global__ void k_fill(const int* __restrict__ V, const int* __restrict__ E) {
    int i = blockIdx.x * blockDim.x + threadIdx.x;
    if (i < NNZ) {
        int e = E[i];
        unsigned pos = atomicAdd(&g_ecur[e], 1u);
        g_eidx[g_eoff[e] + pos] = V[i];
    }
}

// ---------------- K2: build 0.5 * l2norm(x * w_c) features, fp16 hi/lo planes ----------------
__global__ void k_feat(const float* __restrict__ X, const float* __restrict__ W) {
    int r   = blockIdx.x;
    int isE = blockIdx.y;
    int d   = threadIdx.x;   // 128 threads
    __shared__ float red[128];
    float x;
    if (!isE) {
        x = X[(size_t)r * DD + d];
    } else {
        unsigned s0 = g_eoff[r], s1 = g_eoff[r + 1];
        long long acc = 0;
        for (unsigned j = s0; j < s1; j++) {
            int v = g_eidx[j];
            acc += __double2ll_rn((double)X[(size_t)v * DD + d] * 4294967296.0);
        }
        float cnt = (float)(s1 - s0);
        float sum = (float)((double)acc * (1.0 / 4294967296.0));
        x = __fdiv_rn(sum, fmaxf(cnt, 1.0f));
    }
    __half* dhi = isE ? g_Bhi : g_Ahi;
    __half* dlo = isE ? g_Blo : g_Alo;
#pragma unroll
    for (int c = 0; c < CC; c++) {
        float v = x * W[c * DD + d];
        red[d] = v * v;
        __syncthreads();
        for (int s2 = 64; s2 > 0; s2 >>= 1) {
            if (d < s2) red[d] += red[d + s2];
            __syncthreads();
        }
        float nrm = __fsqrt_rn(red[0]);
        __syncthreads();
        float val = 0.5f * __fdiv_rn(v, fmaxf(nrm, 1e-12f));
        __half hi = __float2half_rn(val);
        float rr  = val - __half2float(hi);
        __half lo = __float2half_rn(rr * 2048.0f);
        dhi[(size_t)r * KDIM + c * DD + d] = hi;
        dlo[(size_t)r * KDIM + c * DD + d] = lo;
    }
}

// ---------------- K3: 3-pass FP16 split GEMM  S = A(4096x512) * B(4096x512)^T ----------------
// S = Ahi*Bhi + (Ahi*Blo + Alo*Bhi)/2048 ; 128x128 CTA tile, 16 warps, warp tile 32x32,
// k-chunk 32 (2 x k16 mma steps), double-buffered cp.async.
__global__ void __launch_bounds__(GT, 1) k_gemm() {
    extern __shared__ __align__(128) __half smh[];
    uint32_t sb;
    asm("{ .reg .u64 t; cvta.to.shared.u64 t, %1; cvt.u32.u64 %0, t; }"
        : "=r"(sb) : "l"(smh));
    const int tid = threadIdx.x;
    const int wid = tid >> 5, lane = tid & 31;
    const int g = lane >> 2, t = lane & 3;
    const int wm = wid >> 2, wn = wid & 3;
    const int bm = blockIdx.y * MT, bn = blockIdx.x * NT;

    float accH[2][4][4], accX[2][4][4];
#pragma unroll
    for (int mt = 0; mt < 2; mt++)
#pragma unroll
        for (int nt = 0; nt < 4; nt++)
#pragma unroll
            for (int r = 0; r < 4; r++) { accH[mt][nt][r] = 0.0f; accX[mt][nt][r] = 0.0f; }

    // ---- chunk loader: 4 planes, 128 rows x 64B each; 4 cp.async per thread ----
    auto load_chunk = [&](int kt, int stage) {
        uint32_t base = sb + (uint32_t)stage * (STAGE_H * 2);
        int row = tid >> 2, seg = tid & 3;
        uint32_t so = (uint32_t)(row * (LDKH * 2) + seg * 16);
        size_t goA = (size_t)(bm + row) * KDIM + kt * KCH + seg * 8;
        size_t goB = (size_t)(bn + row) * KDIM + kt * KCH + seg * 8;
        cpa16(base + so,                   g_Ahi + goA);
        cpa16(base + PLANE_H * 2     + so, g_Alo + goA);
        cpa16(base + PLANE_H * 4     + so, g_Bhi + goB);
        cpa16(base + PLANE_H * 6     + so, g_Blo + goB);
        asm volatile("cp.async.commit_group;" ::: "memory");
    };

    load_chunk(0, 0);

    for (int kt = 0; kt < NCHUNK; kt++) {
        int buf = kt & 1;
        if (kt + 1 < NCHUNK) {
            load_chunk(kt + 1, buf ^ 1);
            asm volatile("cp.async.wait_group 1;" ::: "memory");
        } else {
            asm volatile("cp.async.wait_group 0;" ::: "memory");
        }
        __syncthreads();

        const __half* st_ = smh + buf * STAGE_H;
        const __half* Ah = st_;
        const __half* Al = st_ + PLANE_H;
        const __half* Bh = st_ + 2 * PLANE_H;
        const __half* Bl = st_ + 3 * PLANE_H;

#pragma unroll
        for (int ks = 0; ks < 2; ks++) {
            const int kb = ks * 16;
            uint32_t bh[4][2], bl[4][2];
#pragma unroll
            for (int nt = 0; nt < 4; nt++) {
                int n0 = wn * 32 + nt * 8 + g;
                int o  = n0 * LDKH + kb + 2 * t;
                bh[nt][0] = *(const uint32_t*)&Bh[o];
                bh[nt][1] = *(const uint32_t*)&Bh[o + 8];
                bl[nt][0] = *(const uint32_t*)&Bl[o];
                bl[nt][1] = *(const uint32_t*)&Bl[o + 8];
            }
#pragma unroll
            for (int mt = 0; mt < 2; mt++) {
                int r0 = wm * 32 + mt * 16 + g;
                int o0 = r0 * LDKH + kb + 2 * t;
                int o1 = (r0 + 8) * LDKH + kb + 2 * t;
                uint32_t ah0 = *(const uint32_t*)&Ah[o0];
                uint32_t ah1 = *(const uint32_t*)&Ah[o1];
                uint32_t ah2 = *(const uint32_t*)&Ah[o0 + 8];
                uint32_t ah3 = *(const uint32_t*)&Ah[o1 + 8];
                uint32_t al0 = *(const uint32_t*)&Al[o0];
                uint32_t al1 = *(const uint32_t*)&Al[o1];
                uint32_t al2 = *(const uint32_t*)&Al[o0 + 8];
                uint32_t al3 = *(const uint32_t*)&Al[o1 + 8];
#pragma unroll
                for (int nt = 0; nt < 4; nt++) {
                    mma16(accH[mt][nt], ah0, ah1, ah2, ah3, bh[nt][0], bh[nt][1]);
                    mma16(accX[mt][nt], ah0, ah1, ah2, ah3, bl[nt][0], bl[nt][1]);
                    mma16(accX[mt][nt], al0, al1, al2, al3, bh[nt][0], bh[nt][1]);
                }
            }
        }
        __syncthreads();
    }

    // ---- epilogue: S = accH + accX/2048 ; c0:(g,2t) c1:(g,2t+1) c2:(g+8,2t) c3:(g+8,2t+1)
    const float IS = 1.0f / 2048.0f;
#pragma unroll
    for (int mt = 0; mt < 2; mt++) {
        int r0 = bm + wm * 32 + mt * 16 + g;
#pragma unroll
        for (int nt = 0; nt < 4; nt++) {
            int c = bn + wn * 32 + nt * 8 + 2 * t;
            float v0 = fmaf(accX[mt][nt][0], IS, accH[mt][nt][0]);
            float v1 = fmaf(accX[mt][nt][1], IS, accH[mt][nt][1]);
            float v2 = fmaf(accX[mt][nt][2], IS, accH[mt][nt][2]);
            float v3 = fmaf(accX[mt][nt][3], IS, accH[mt][nt][3]);
            *(float2*)(g_S + (size_t)r0 * MMm + c)       = make_float2(v0, v1);
            *(float2*)(g_S + (size_t)(r0 + 8) * MMm + c) = make_float2(v2, v3);
        }
    }
}

// ---------------- K4: mask existing incidences (dedup-safe) ----------------
__global__ void k_mask(const int* __restrict__ V, const int* __restrict__ E) {
    int i = blockIdx.x * blockDim.x + threadIdx.x;
    if (i < NNZ) {
        atomicExch(&g_S[(size_t)V[i] * MMm + E[i]], -1e30f);
    }
}

// ---------------- K5: top-11-bit histogram ----------------
__global__ void k_hist() {
    __shared__ unsigned h[2048];
    for (int j = threadIdx.x; j < 2048; j += blockDim.x) h[j] = 0;
    __syncthreads();
    int i  = blockIdx.x * blockDim.x + threadIdx.x;
    int st = gridDim.x * blockDim.x;
    const float4* S4 = (const float4*)g_S;
    for (int j = i; j < NM / 4; j += st) {
        float4 s = S4[j];
        atomicAdd(&h[f2ord(s.x) >> 21], 1u);
        atomicAdd(&h[f2ord(s.y) >> 21], 1u);
        atomicAdd(&h[f2ord(s.z) >> 21], 1u);
        atomicAdd(&h[f2ord(s.w) >> 21], 1u);
    }
    __syncthreads();
    for (int j = threadIdx.x; j < 2048; j += blockDim.x)
        if (h[j]) atomicAdd(&g_hist[j], h[j]);
}

// ---------------- K6: find threshold bucket (1 block, 1024 thr) ----------------
__global__ void k_pick() {
    __shared__ unsigned c[2048];
    int t = threadIdx.x;
    c[t] = g_hist[t];
    c[t + 1024] = g_hist[t + 1024];
    __syncthreads();
    for (int off = 1; off < 2048; off <<= 1) {
        unsigned a0 = (t + off < 2048) ? c[t + off] : 0u;
        unsigned a1 = (t + 1024 + off < 2048) ? c[t + 1024 + off] : 0u;
        __syncthreads();
        c[t] += a0; c[t + 1024] += a1;
        __syncthreads();
    }
    for (int b = t; b < 2048; b += 1024) {
        unsigned cum = c[b], nxt = (b + 1 < 2048) ? c[b + 1] : 0u;
        if (cum >= (unsigned)KADD && nxt < (unsigned)KADD) {
            g_B1 = (unsigned)b;
            g_r1 = (unsigned)KADD - nxt;
        }
    }
}

// ---------------- K7: collect candidates in threshold bucket ----------------
__global__ void k_collect() {
    unsigned B1 = g_B1;
    int i  = blockIdx.x * blockDim.x + threadIdx.x;
    int st = gridDim.x * blockDim.x;
    const float4* S4 = (const float4*)g_S;
    for (int j = i; j < NM / 4; j += st) {
        float4 s = S4[j];
        unsigned u0 = f2ord(s.x), u1 = f2ord(s.y), u2 = f2ord(s.z), u3 = f2ord(s.w);
        if ((u0 >> 21) == B1) { unsigned p = atomicAdd(&g_candCount, 1u); if (p < CAPC) g_cand[p] = u0; }
        if ((u1 >> 21) == B1) { unsigned p = atomicAdd(&g_candCount, 1u); if (p < CAPC) g_cand[p] = u1; }
        if ((u2 >> 21) == B1) { unsigned p = atomicAdd(&g_candCount, 1u); if (p < CAPC) g_cand[p] = u2; }
        if ((u3 >> 21) == B1) { unsigned p = atomicAdd(&g_candCount, 1u); if (p < CAPC) g_cand[p] = u3; }
    }
}

// ---------------- K8: exact k-th value via 11+10 bit refine (1 block) ----------------
__global__ void k_select() {
    __shared__ unsigned h[2048];
    __shared__ unsigned sb2, sr2;
    int t = threadIdx.x;  // 1024
    unsigned nc = g_candCount; if (nc > CAPC) nc = CAPC;
    unsigned r1 = g_r1;

    h[t] = 0; h[t + 1024] = 0;
    __syncthreads();
    for (unsigned i = t; i < nc; i += 1024)
        atomicAdd(&h[(g_cand[i] >> 10) & 2047u], 1u);
    __syncthreads();
    for (int off = 1; off < 2048; off <<= 1) {
        unsigned a0 = (t + off < 2048) ? h[t + off] : 0u;
        unsigned a1 = (t + 1024 + off < 2048) ? h[t + 1024 + off] : 0u;
        __syncthreads();
        h[t] += a0; h[t + 1024] += a1;
        __syncthreads();
    }
    for (int b = t; b < 2048; b += 1024) {
        unsigned cum = h[b], nxt = (b + 1 < 2048) ? h[b + 1] : 0u;
        if (cum >= r1 && nxt < r1) { sb2 = (unsigned)b; sr2 = r1 - nxt; }
    }
    __syncthreads();
    unsigned b2 = sb2, r2 = sr2;

    h[t] = 0;
    __syncthreads();
    for (unsigned i = t; i < nc; i += 1024) {
        unsigned u = g_cand[i];
        if (((u >> 10) & 2047u) == b2) atomicAdd(&h[u & 1023u], 1u);
    }
    __syncthreads();
    for (int off = 1; off < 1024; off <<= 1) {
        unsigned a = (t + off < 1024) ? h[t + off] : 0u;
        __syncthreads();
        h[t] += a;
        __syncthreads();
    }
    unsigned cum = h[t], nxt = (t + 1 < 1024) ? h[t + 1] : 0u;
    if (cum >= r2 && nxt < r2)
        g_Tbits = (g_B1 << 21) | (b2 << 10) | (unsigned)t;
}

// ---------------- K9: fused output ----------------
__device__ __forceinline__ float outval(float h, float p, float e, float s, unsigned T) {
    float enr = h + ((f2ord(s) >= T) ? 1.0f : 0.0f);
    float pa = __fadd_rn(p, 1e-8f);
    float pb = __fadd_rn(__fsub_rn(1.0f, p), 1e-8f);
    float eb = __fsub_rn(1.0f, e);
    double lhs = (double)e  * (double)pa;
    double rhs = (double)eb * (double)pb;
    return (lhs > rhs) ? enr : 0.0f;
}

__global__ void k_final(const float* __restrict__ H, const float* __restrict__ P,
                        const float* __restrict__ Eps, float* __restrict__ out) {
    unsigned T = g_Tbits;
    int i  = blockIdx.x * blockDim.x + threadIdx.x;
    int st = gridDim.x * blockDim.x;
    const float4* H4 = (const float4*)H;
    const float4* P4 = (const float4*)P;
    const float4* E4 = (const float4*)Eps;
    const float4* S4 = (const float4*)g_S;
    float4* O4 = (float4*)out;
    for (int j = i; j < NM / 4; j += st) {
        float4 h4 = H4[j], p4 = P4[j], e4 = E4[j], s4 = S4[j];
        float4 o;
        o.x = outval(h4.x, p4.x, e4.x, s4.x, T);
        o.y = outval(h4.y, p4.y, e4.y, s4.y, T);
        o.z = outval(h4.z, p4.z, e4.z, s4.z, T);
        o.w = outval(h4.w, p4.w, e4.w, s4.w, T);
        O4[j] = o;
    }
}

// ---------------- launch ----------------
extern "C" void kernel_launch(void* const* d_in, const int* in_sizes, int n_in,
                              void* d_out, int out_size) {
    const float* X   = (const float*)d_in[0];
    const float* H   = (const float*)d_in[1];
    const int*   V   = (const int*)d_in[2];
    const int*   E   = (const int*)d_in[3];
    const float* P   = (const float*)d_in[4];
    const float* W   = (const float*)d_in[5];
    const float* Eps = (const float*)d_in[6];
    float* out = (float*)d_out;

    cudaFuncSetAttribute(k_gemm, cudaFuncAttributeMaxDynamicSharedMemorySize, SMEM_BYTES);

    k_zero<<<64, 256>>>();
    k_count<<<NNZ / 256, 256>>>(E);
    k_prefix<<<1, 1024>>>();
    k_fill<<<NNZ / 256, 256>>>(V, E);
    {
        dim3 fg(NN, 2);
        k_feat<<<fg, 128>>>(X, W);
    }
    {
        dim3 gg(MMm / NT, NN / MT);   // (32, 32)
        k_gemm<<<gg, GT, SMEM_BYTES>>>();
    }
    k_mask<<<NNZ / 256, 256>>>(V, E);
    k_hist<<<2048, 256>>>();
    k_pick<<<1, 1024>>>();
    k_collect<<<2048, 256>>>();
    k_select<<<1, 1024>>>();
    k_final<<<4096, 256>>>(H, P, Eps, out);
}

// round 12
// speedup vs baseline: 1.6135x; 1.0120x over previous
#include <cuda_runtime.h>
#include <cuda_fp16.h>
#include <cstdint>

#define NN   4096
#define MMm  4096
#define DD   128
#define CC   4
#define NNZ  262144
#define KDIM 512
#define KADD 26214
#define NM   (NN * MMm)
#define CAPC (4u * 1024u * 1024u)

// GEMM tiling (mma.sync fp16 m16n8k16, 2-term split)
#define MT      128
#define NT      128
#define KCH     32
#define NCHUNK  (KDIM / KCH)          // 16
#define LDKH    40                    // padded k-stride in halves (32+8) -> conflict-free ldmatrix
#define PLANE_H (128 * LDKH)          // 5120 halves per plane
#define STAGE_H (4 * PLANE_H)         // 20480 halves per stage
#define SMEM_BYTES (2 * STAGE_H * 2)  // 81920 bytes
#define GT      512                   // gemm threads

// ---------------- scratch (static device memory; no allocs allowed) ----------------
__device__ int       g_cnt[MMm];             // segment counts
__device__ unsigned  g_eoff[MMm + 1];        // CSR offsets
__device__ unsigned  g_ecur[MMm];            // fill cursors
__device__ int       g_eidx[NNZ];            // CSR node indices
__device__ __half    g_Ahi[NN * KDIM];       // node feature fp16 hi plane
__device__ __half    g_Alo[NN * KDIM];       // node feature fp16 lo*2048 plane
__device__ __half    g_Bhi[MMm * KDIM];      // edge feature fp16 hi plane
__device__ __half    g_Blo[MMm * KDIM];      // edge feature fp16 lo*2048 plane
__device__ float     g_S[NM];                // similarity matrix (masked)
__device__ unsigned  g_hist[2048];
__device__ unsigned  g_cand[CAPC];
__device__ unsigned  g_candCount;
__device__ unsigned  g_B1;
__device__ unsigned  g_r1;
__device__ unsigned  g_Tbits;

__device__ __forceinline__ unsigned f2ord(float f) {
    unsigned u = __float_as_uint(f);
    return (u & 0x80000000u) ? ~u : (u | 0x80000000u);
}
__device__ __forceinline__ void cpa16(uint32_t dst, const void* src) {
    asm volatile("cp.async.cg.shared.global [%0], [%1], 16;"
                 :: "r"(dst), "l"(__cvta_generic_to_global(src)) : "memory");
}
// m16n8k16 fp16 mma: D = A*B + D  (row.col), fp32 accumulate
__device__ __forceinline__ void mma16(float* c,
                                      uint32_t a0, uint32_t a1, uint32_t a2, uint32_t a3,
                                      uint32_t b0, uint32_t b1) {
    asm volatile(
        "mma.sync.aligned.m16n8k16.row.col.f32.f16.f16.f32 "
        "{%0,%1,%2,%3}, {%4,%5,%6,%7}, {%8,%9}, {%0,%1,%2,%3};"
        : "+f"(c[0]), "+f"(c[1]), "+f"(c[2]), "+f"(c[3])
        : "r"(a0), "r"(a1), "r"(a2), "r"(a3), "r"(b0), "r"(b1));
}
__device__ __forceinline__ void ldsm4(uint32_t& r0, uint32_t& r1, uint32_t& r2, uint32_t& r3,
                                      uint32_t addr) {
    asm volatile("ldmatrix.sync.aligned.m8n8.x4.shared.b16 {%0,%1,%2,%3}, [%4];"
                 : "=r"(r0), "=r"(r1), "=r"(r2), "=r"(r3) : "r"(addr));
}

// ---------------- K0: zero transient state (runs every replay) ----------------
__global__ void k_zero() {
    int i  = blockIdx.x * blockDim.x + threadIdx.x;
    int st = gridDim.x * blockDim.x;
    for (int j = i; j < MMm;  j += st) { g_cnt[j] = 0; g_ecur[j] = 0; }
    for (int j = i; j < 2048; j += st) g_hist[j] = 0;
    if (i == 0) g_candCount = 0;
}

// ---------------- CSR build: count -> prefix -> fill ----------------
__global__ void k_count(const int* __restrict__ E) {
    int i = blockIdx.x * blockDim.x + threadIdx.x;
    if (i < NNZ) atomicAdd(&g_cnt[E[i]], 1);
}

__global__ void k_prefix() {   // exclusive prefix of g_cnt into g_eoff (1 block, 1024 thr)
    __shared__ unsigned s[1024];
    int t = threadIdx.x;
    unsigned c0 = g_cnt[4*t], c1 = g_cnt[4*t+1], c2 = g_cnt[4*t+2], c3 = g_cnt[4*t+3];
    s[t] = c0 + c1 + c2 + c3;
    __syncthreads();
    for (int off = 1; off < 1024; off <<= 1) {
        unsigned v = (t >= off) ? s[t - off] : 0u;
        __syncthreads();
        s[t] += v;
        __syncthreads();
    }
    unsigned base = t ? s[t-1] : 0u;
    g_eoff[4*t]   = base;
    g_eoff[4*t+1] = base + c0;
    g_eoff[4*t+2] = base + c0 + c1;
    g_eoff[4*t+3] = base + c0 + c1 + c2;
    if (t == 1023) g_eoff[MMm] = s[1023];
}

__global__ void k_fill(const int* __restrict__ V, const int* __restrict__ E) {
    int i = blockIdx.x * blockDim.x + threadIdx.x;
    if (i < NNZ) {
        int e = E[i];
        unsigned pos = atomicAdd(&g_ecur[e], 1u);
        g_eidx[g_eoff[e] + pos] = V[i];
    }
}

// ---------------- K2: build 0.5 * l2norm(x * w_c) features, fp16 hi/lo planes ----------------
__global__ void k_feat(const float* __restrict__ X, const float* __restrict__ W) {
    int r   = blockIdx.x;
    int isE = blockIdx.y;
    int d   = threadIdx.x;   // 128 threads
    __shared__ float red[128];
    float x;
    if (!isE) {
        x = X[(size_t)r * DD + d];
    } else {
        unsigned s0 = g_eoff[r], s1 = g_eoff[r + 1];
        long long acc = 0;
        for (unsigned j = s0; j < s1; j++) {
            int v = g_eidx[j];
            acc += __double2ll_rn((double)X[(size_t)v * DD + d] * 4294967296.0);
        }
        float cnt = (float)(s1 - s0);
        float sum = (float)((double)acc * (1.0 / 4294967296.0));
        x = __fdiv_rn(sum, fmaxf(cnt, 1.0f));
    }
    __half* dhi = isE ? g_Bhi : g_Ahi;
    __half* dlo = isE ? g_Blo : g_Alo;
#pragma unroll
    for (int c = 0; c < CC; c++) {
        float v = x * W[c * DD + d];
        red[d] = v * v;
        __syncthreads();
        for (int s2 = 64; s2 > 0; s2 >>= 1) {
            if (d < s2) red[d] += red[d + s2];
            __syncthreads();
        }
        float nrm = __fsqrt_rn(red[0]);
        __syncthreads();
        float val = 0.5f * __fdiv_rn(v, fmaxf(nrm, 1e-12f));
        __half hi = __float2half_rn(val);
        float rr  = val - __half2float(hi);
        __half lo = __float2half_rn(rr * 2048.0f);
        dhi[(size_t)r * KDIM + c * DD + d] = hi;
        dlo[(size_t)r * KDIM + c * DD + d] = lo;
    }
}

// ---------------- K3: 3-pass FP16 split GEMM  S = A(4096x512) * B(4096x512)^T ----------------
// S = Ahi*Bhi + (Ahi*Blo + Alo*Bhi)/2048 ; 128x128 CTA tile, 16 warps, warp tile 32x32,
// k-chunk 32 (2 x k16 mma steps), double-buffered cp.async, ldmatrix fragment loads.
__global__ void __launch_bounds__(GT, 1) k_gemm() {
    extern __shared__ __align__(128) __half smh[];
    uint32_t sb;
    asm("{ .reg .u64 t; cvta.to.shared.u64 t, %1; cvt.u32.u64 %0, t; }"
        : "=r"(sb) : "l"(smh));
    const int tid = threadIdx.x;
    const int wid = tid >> 5, lane = tid & 31;
    const int g = lane >> 2, t = lane & 3;
    const int wm = wid >> 2, wn = wid & 3;
    const int bm = blockIdx.y * MT, bn = blockIdx.x * NT;

    float accH[2][4][4], accX[2][4][4];
#pragma unroll
    for (int mt = 0; mt < 2; mt++)
#pragma unroll
        for (int nt = 0; nt < 4; nt++)
#pragma unroll
            for (int r = 0; r < 4; r++) { accH[mt][nt][r] = 0.0f; accX[mt][nt][r] = 0.0f; }

    // ---- ldmatrix lane-address bases (byte offsets within a stage) ----
    // A x4 tile (16x16): lane L -> row base+(L&15), kcol (L>>4)*8
    // B x4 (two n8-tiles): lane L -> row NB+(L&7)+((L>>4)&1)*8, kcol ((L>>3)&1)*8
    const int aRow = wm * 32 + (lane & 15);
    const int aK   = (lane >> 4) * 8;
    const uint32_t aOff0 = (uint32_t)((aRow)      * LDKH + aK) * 2;
    const uint32_t aOff1 = (uint32_t)((aRow + 16) * LDKH + aK) * 2;
    const int bRow = wn * 32 + (lane & 7) + ((lane >> 4) & 1) * 8;
    const int bK   = ((lane >> 3) & 1) * 8;
    const uint32_t bOff0 = (uint32_t)((bRow)      * LDKH + bK) * 2;
    const uint32_t bOff1 = (uint32_t)((bRow + 16) * LDKH + bK) * 2;

    // ---- chunk loader: 4 planes, 128 rows x 64B each; 4 cp.async per thread ----
    auto load_chunk = [&](int kt, int stage) {
        uint32_t base = sb + (uint32_t)stage * (STAGE_H * 2);
        int row = tid >> 2, seg = tid & 3;
        uint32_t so = (uint32_t)(row * (LDKH * 2) + seg * 16);
        size_t goA = (size_t)(bm + row) * KDIM + kt * KCH + seg * 8;
        size_t goB = (size_t)(bn + row) * KDIM + kt * KCH + seg * 8;
        cpa16(base + so,                   g_Ahi + goA);
        cpa16(base + PLANE_H * 2     + so, g_Alo + goA);
        cpa16(base + PLANE_H * 4     + so, g_Bhi + goB);
        cpa16(base + PLANE_H * 6     + so, g_Blo + goB);
        asm volatile("cp.async.commit_group;" ::: "memory");
    };

    load_chunk(0, 0);

    for (int kt = 0; kt < NCHUNK; kt++) {
        int buf = kt & 1;
        if (kt + 1 < NCHUNK) {
            load_chunk(kt + 1, buf ^ 1);
            asm volatile("cp.async.wait_group 1;" ::: "memory");
        } else {
            asm volatile("cp.async.wait_group 0;" ::: "memory");
        }
        __syncthreads();

        uint32_t stg = sb + (uint32_t)buf * (STAGE_H * 2);

#pragma unroll
        for (int ks = 0; ks < 2; ks++) {
            const uint32_t kboff = (uint32_t)ks * 32;   // 16 halves = 32 bytes
            uint32_t bh[4][2], bl[4][2];
            // B hi/lo: two x4 each (n-tiles {0,1} and {2,3})
            ldsm4(bh[0][0], bh[0][1], bh[1][0], bh[1][1], stg + PLANE_H * 4 + bOff0 + kboff);
            ldsm4(bh[2][0], bh[2][1], bh[3][0], bh[3][1], stg + PLANE_H * 4 + bOff1 + kboff);
            ldsm4(bl[0][0], bl[0][1], bl[1][0], bl[1][1], stg + PLANE_H * 6 + bOff0 + kboff);
            ldsm4(bl[2][0], bl[2][1], bl[3][0], bl[3][1], stg + PLANE_H * 6 + bOff1 + kboff);
#pragma unroll
            for (int mt = 0; mt < 2; mt++) {
                uint32_t aoff = (mt == 0) ? aOff0 : aOff1;
                uint32_t ah0, ah1, ah2, ah3, al0, al1, al2, al3;
                ldsm4(ah0, ah1, ah2, ah3, stg +               aoff + kboff);
                ldsm4(al0, al1, al2, al3, stg + PLANE_H * 2 + aoff + kboff);
#pragma unroll
                for (int nt = 0; nt < 4; nt++) {
                    mma16(accH[mt][nt], ah0, ah1, ah2, ah3, bh[nt][0], bh[nt][1]);
                    mma16(accX[mt][nt], ah0, ah1, ah2, ah3, bl[nt][0], bl[nt][1]);
                    mma16(accX[mt][nt], al0, al1, al2, al3, bh[nt][0], bh[nt][1]);
                }
            }
        }
        __syncthreads();
    }

    // ---- epilogue: S = accH + accX/2048 ; c0:(g,2t) c1:(g,2t+1) c2:(g+8,2t) c3:(g+8,2t+1)
    const float IS = 1.0f / 2048.0f;
#pragma unroll
    for (int mt = 0; mt < 2; mt++) {
        int r0 = bm + wm * 32 + mt * 16 + g;
#pragma unroll
        for (int nt = 0; nt < 4; nt++) {
            int c = bn + wn * 32 + nt * 8 + 2 * t;
            float v0 = fmaf(accX[mt][nt][0], IS, accH[mt][nt][0]);
            float v1 = fmaf(accX[mt][nt][1], IS, accH[mt][nt][1]);
            float v2 = fmaf(accX[mt][nt][2], IS, accH[mt][nt][2]);
            float v3 = fmaf(accX[mt][nt][3], IS, accH[mt][nt][3]);
            *(float2*)(g_S + (size_t)r0 * MMm + c)       = make_float2(v0, v1);
            *(float2*)(g_S + (size_t)(r0 + 8) * MMm + c) = make_float2(v2, v3);
        }
    }
}

// ---------------- K4: mask existing incidences (dedup-safe) ----------------
__global__ void k_mask(const int* __restrict__ V, const int* __restrict__ E) {
    int i = blockIdx.x * blockDim.x + threadIdx.x;
    if (i < NNZ) {
        atomicExch(&g_S[(size_t)V[i] * MMm + E[i]], -1e30f);
    }
}

// ---------------- K5: top-11-bit histogram ----------------
__global__ void k_hist() {
    __shared__ unsigned h[2048];
    for (int j = threadIdx.x; j < 2048; j += blockDim.x) h[j] = 0;
    __syncthreads();
    int i  = blockIdx.x * blockDim.x + threadIdx.x;
    int st = gridDim.x * blockDim.x;
    const float4* S4 = (const float4*)g_S;
    for (int j = i; j < NM / 4; j += st) {
        float4 s = S4[j];
        atomicAdd(&h[f2ord(s.x) >> 21], 1u);
        atomicAdd(&h[f2ord(s.y) >> 21], 1u);
        atomicAdd(&h[f2ord(s.z) >> 21], 1u);
        atomicAdd(&h[f2ord(s.w) >> 21], 1u);
    }
    __syncthreads();
    for (int j = threadIdx.x; j < 2048; j += blockDim.x)
        if (h[j]) atomicAdd(&g_hist[j], h[j]);
}

// ---------------- K6: find threshold bucket (1 block, 1024 thr) ----------------
__global__ void k_pick() {
    __shared__ unsigned c[2048];
    int t = threadIdx.x;
    c[t] = g_hist[t];
    c[t + 1024] = g_hist[t + 1024];
    __syncthreads();
    for (int off = 1; off < 2048; off <<= 1) {
        unsigned a0 = (t + off < 2048) ? c[t + off] : 0u;
        unsigned a1 = (t + 1024 + off < 2048) ? c[t + 1024 + off] : 0u;
        __syncthreads();
        c[t] += a0; c[t + 1024] += a1;
        __syncthreads();
    }
    for (int b = t; b < 2048; b += 1024) {
        unsigned cum = c[b], nxt = (b + 1 < 2048) ? c[b + 1] : 0u;
        if (cum >= (unsigned)KADD && nxt < (unsigned)KADD) {
            g_B1 = (unsigned)b;
            g_r1 = (unsigned)KADD - nxt;
        }
    }
}

// ---------------- K7: collect candidates in threshold bucket ----------------
__global__ void k_collect() {
    unsigned B1 = g_B1;
    int i  = blockIdx.x * blockDim.x + threadIdx.x;
    int st = gridDim.x * blockDim.x;
    const float4* S4 = (const float4*)g_S;
    for (int j = i; j < NM / 4; j += st) {
        float4 s = S4[j];
        unsigned u0 = f2ord(s.x), u1 = f2ord(s.y), u2 = f2ord(s.z), u3 = f2ord(s.w);
        if ((u0 >> 21) == B1) { unsigned p = atomicAdd(&g_candCount, 1u); if (p < CAPC) g_cand[p] = u0; }
        if ((u1 >> 21) == B1) { unsigned p = atomicAdd(&g_candCount, 1u); if (p < CAPC) g_cand[p] = u1; }
        if ((u2 >> 21) == B1) { unsigned p = atomicAdd(&g_candCount, 1u); if (p < CAPC) g_cand[p] = u2; }
        if ((u3 >> 21) == B1) { unsigned p = atomicAdd(&g_candCount, 1u); if (p < CAPC) g_cand[p] = u3; }
    }
}

// ---------------- K8: exact k-th value via 11+10 bit refine (1 block) ----------------
__global__ void k_select() {
    __shared__ unsigned h[2048];
    __shared__ unsigned sb2, sr2;
    int t = threadIdx.x;  // 1024
    unsigned nc = g_candCount; if (nc > CAPC) nc = CAPC;
    unsigned r1 = g_r1;

    h[t] = 0; h[t + 1024] = 0;
    __syncthreads();
    for (unsigned i = t; i < nc; i += 1024)
        atomicAdd(&h[(g_cand[i] >> 10) & 2047u], 1u);
    __syncthreads();
    for (int off = 1; off < 2048; off <<= 1) {
        unsigned a0 = (t + off < 2048) ? h[t + off] : 0u;
        unsigned a1 = (t + 1024 + off < 2048) ? h[t + 1024 + off] : 0u;
        __syncthreads();
        h[t] += a0; h[t + 1024] += a1;
        __syncthreads();
    }
    for (int b = t; b < 2048; b += 1024) {
        unsigned cum = h[b], nxt = (b + 1 < 2048) ? h[b + 1] : 0u;
        if (cum >= r1 && nxt < r1) { sb2 = (unsigned)b; sr2 = r1 - nxt; }
    }
    __syncthreads();
    unsigned b2 = sb2, r2 = sr2;

    h[t] = 0;
    __syncthreads();
    for (unsigned i = t; i < nc; i += 1024) {
        unsigned u = g_cand[i];
        if (((u >> 10) & 2047u) == b2) atomicAdd(&h[u & 1023u], 1u);
    }
    __syncthreads();
    for (int off = 1; off < 1024; off <<= 1) {
        unsigned a = (t + off < 1024) ? h[t + off] : 0u;
        __syncthreads();
        h[t] += a;
        __syncthreads();
    }
    unsigned cum = h[t], nxt = (t + 1 < 1024) ? h[t + 1] : 0u;
    if (cum >= r2 && nxt < r2)
        g_Tbits = (g_B1 << 21) | (b2 << 10) | (unsigned)t;
}

// ---------------- K9: fused output ----------------
__device__ __forceinline__ float outval(float h, float p, float e, float s, unsigned T) {
    float enr = h + ((f2ord(s) >= T) ? 1.0f : 0.0f);
    float pa = __fadd_rn(p, 1e-8f);
    float pb = __fadd_rn(__fsub_rn(1.0f, p), 1e-8f);
    float eb = __fsub_rn(1.0f, e);
    double lhs = (double)e  * (double)pa;
    double rhs = (double)eb * (double)pb;
    return (lhs > rhs) ? enr : 0.0f;
}

__global__ void k_final(const float* __restrict__ H, const float* __restrict__ P,
                        const float* __restrict__ Eps, float* __restrict__ out) {
    unsigned T = g_Tbits;
    int i  = blockIdx.x * blockDim.x + threadIdx.x;
    int st = gridDim.x * blockDim.x;
    const float4* H4 = (const float4*)H;
    const float4* P4 = (const float4*)P;
    const float4* E4 = (const float4*)Eps;
    const float4* S4 = (const float4*)g_S;
    float4* O4 = (float4*)out;
    for (int j = i; j < NM / 4; j += st) {
        float4 h4 = H4[j], p4 = P4[j], e4 = E4[j], s4 = S4[j];
        float4 o;
        o.x = outval(h4.x, p4.x, e4.x, s4.x, T);
        o.y = outval(h4.y, p4.y, e4.y, s4.y, T);
        o.z = outval(h4.z, p4.z, e4.z, s4.z, T);
        o.w = outval(h4.w, p4.w, e4.w, s4.w, T);
        O4[j] = o;
    }
}

// ---------------- launch ----------------
extern "C" void kernel_launch(void* const* d_in, const int* in_sizes, int n_in,
                              void* d_out, int out_size) {
    const float* X   = (const float*)d_in[0];
    const float* H   = (const float*)d_in[1];
    const int*   V   = (const int*)d_in[2];
    const int*   E   = (const int*)d_in[3];
    const float* P   = (const float*)d_in[4];
    const float* W   = (const float*)d_in[5];
    const float* Eps = (const float*)d_in[6];
    float* out = (float*)d_out;

    cudaFuncSetAttribute(k_gemm, cudaFuncAttributeMaxDynamicSharedMemorySize, SMEM_BYTES);

    k_zero<<<64, 256>>>();
    k_count<<<NNZ / 256, 256>>>(E);
    k_prefix<<<1, 1024>>>();
    k_fill<<<NNZ / 256, 256>>>(V, E);
    {
        dim3 fg(NN, 2);
        k_feat<<<fg, 128>>>(X, W);
    }
    {
        dim3 gg(MMm / NT, NN / MT);   // (32, 32)
        k_gemm<<<gg, GT, SMEM_BYTES>>>();
    }
    k_mask<<<NNZ / 256, 256>>>(V, E);
    k_hist<<<2048, 256>>>();
    k_pick<<<1, 1024>>>();
    k_collect<<<2048, 256>>>();
    k_select<<<1, 1024>>>();
    k_final<<<4096, 256>>>(H, P, Eps, out);
}

// round 13
// speedup vs baseline: 1.6220x; 1.0053x over previous
#include <cuda_runtime.h>
#include <cuda_fp16.h>
#include <cstdint>

#define NN   4096
#define MMm  4096
#define DD   128
#define CC   4
#define NNZ  262144
#define KDIM 512
#define KADD 26214
#define NM   (NN * MMm)
#define CAPC (4u * 1024u * 1024u)

// GEMM tiling (mma.sync fp16 m16n8k16, 2-term split)
#define MT      128
#define NT      128
#define KCH     32
#define NCHUNK  (KDIM / KCH)          // 16
#define LDKH    40                    // padded k-stride in halves (32+8) -> conflict-free ldmatrix
#define PLANE_H (128 * LDKH)          // 5120 halves per plane
#define STAGE_H (4 * PLANE_H)         // 20480 halves per stage
#define SMEM_BYTES (2 * STAGE_H * 2)  // 81920 bytes
#define GT      512                   // gemm threads

// ---------------- scratch (static device memory; no allocs allowed) ----------------
__device__ int       g_cnt[MMm];             // segment counts
__device__ unsigned  g_eoff[MMm + 1];        // CSR offsets
__device__ unsigned  g_ecur[MMm];            // fill cursors
__device__ int       g_eidx[NNZ];            // CSR node indices
__device__ __half    g_Ahi[NN * KDIM];       // node feature fp16 hi plane
__device__ __half    g_Alo[NN * KDIM];       // node feature fp16 lo*2048 plane
__device__ __half    g_Bhi[MMm * KDIM];      // edge feature fp16 hi plane
__device__ __half    g_Blo[MMm * KDIM];      // edge feature fp16 lo*2048 plane
__device__ float     g_S[NM];                // similarity matrix (masked)
__device__ unsigned  g_hist[2048];
__device__ unsigned  g_cand[CAPC];
__device__ unsigned  g_candCount;
__device__ unsigned  g_B1;
__device__ unsigned  g_r1;
__device__ unsigned  g_Tbits;

__device__ __forceinline__ unsigned f2ord(float f) {
    unsigned u = __float_as_uint(f);
    return (u & 0x80000000u) ? ~u : (u | 0x80000000u);
}
__device__ __forceinline__ void cpa16(uint32_t dst, const void* src) {
    asm volatile("cp.async.cg.shared.global [%0], [%1], 16;"
                 :: "r"(dst), "l"(__cvta_generic_to_global(src)) : "memory");
}
// m16n8k16 fp16 mma: D = A*B + D  (row.col), fp32 accumulate
__device__ __forceinline__ void mma16(float* c,
                                      uint32_t a0, uint32_t a1, uint32_t a2, uint32_t a3,
                                      uint32_t b0, uint32_t b1) {
    asm volatile(
        "mma.sync.aligned.m16n8k16.row.col.f32.f16.f16.f32 "
        "{%0,%1,%2,%3}, {%4,%5,%6,%7}, {%8,%9}, {%0,%1,%2,%3};"
        : "+f"(c[0]), "+f"(c[1]), "+f"(c[2]), "+f"(c[3])
        : "r"(a0), "r"(a1), "r"(a2), "r"(a3), "r"(b0), "r"(b1));
}
__device__ __forceinline__ void ldsm4(uint32_t& r0, uint32_t& r1, uint32_t& r2, uint32_t& r3,
                                      uint32_t addr) {
    asm volatile("ldmatrix.sync.aligned.m8n8.x4.shared.b16 {%0,%1,%2,%3}, [%4];"
                 : "=r"(r0), "=r"(r1), "=r"(r2), "=r"(r3) : "r"(addr));
}

// ---------------- K0: zero transient state (runs every replay) ----------------
__global__ void k_zero() {
    int i  = blockIdx.x * blockDim.x + threadIdx.x;
    int st = gridDim.x * blockDim.x;
    for (int j = i; j < MMm;  j += st) { g_cnt[j] = 0; g_ecur[j] = 0; }
    for (int j = i; j < 2048; j += st) g_hist[j] = 0;
    if (i == 0) g_candCount = 0;
}

// ---------------- CSR build: count -> prefix -> fill ----------------
__global__ void k_count(const int* __restrict__ E) {
    int i = blockIdx.x * blockDim.x + threadIdx.x;
    if (i < NNZ) atomicAdd(&g_cnt[E[i]], 1);
}

__global__ void k_prefix() {   // exclusive prefix of g_cnt into g_eoff (1 block, 1024 thr)
    __shared__ unsigned s[1024];
    int t = threadIdx.x;
    unsigned c0 = g_cnt[4*t], c1 = g_cnt[4*t+1], c2 = g_cnt[4*t+2], c3 = g_cnt[4*t+3];
    s[t] = c0 + c1 + c2 + c3;
    __syncthreads();
    for (int off = 1; off < 1024; off <<= 1) {
        unsigned v = (t >= off) ? s[t - off] : 0u;
        __syncthreads();
        s[t] += v;
        __syncthreads();
    }
    unsigned base = t ? s[t-1] : 0u;
    g_eoff[4*t]   = base;
    g_eoff[4*t+1] = base + c0;
    g_eoff[4*t+2] = base + c0 + c1;
    g_eoff[4*t+3] = base + c0 + c1 + c2;
    if (t == 1023) g_eoff[MMm] = s[1023];
}

__global__ void k_fill(const int* __restrict__ V, const int* __restrict__ E) {
    int i = blockIdx.x * blockDim.x + threadIdx.x;
    if (i < NNZ) {
        int e = E[i];
        unsigned pos = atomicAdd(&g_ecur[e], 1u);
        g_eidx[g_eoff[e] + pos] = V[i];
    }
}

// ---------------- K2: build 0.5 * l2norm(x * w_c) features, fp16 hi/lo planes ----------------
__global__ void k_feat(const float* __restrict__ X, const float* __restrict__ W) {
    int r   = blockIdx.x;
    int isE = blockIdx.y;
    int d   = threadIdx.x;   // 128 threads
    __shared__ float red[128];
    float x;
    if (!isE) {
        x = X[(size_t)r * DD + d];
    } else {
        unsigned s0 = g_eoff[r], s1 = g_eoff[r + 1];
        long long acc = 0;
        for (unsigned j = s0; j < s1; j++) {
            int v = g_eidx[j];
            acc += __double2ll_rn((double)X[(size_t)v * DD + d] * 4294967296.0);
        }
        float cnt = (float)(s1 - s0);
        float sum = (float)((double)acc * (1.0 / 4294967296.0));
        x = __fdiv_rn(sum, fmaxf(cnt, 1.0f));
    }
    __half* dhi = isE ? g_Bhi : g_Ahi;
    __half* dlo = isE ? g_Blo : g_Alo;
#pragma unroll
    for (int c = 0; c < CC; c++) {
        float v = x * W[c * DD + d];
        red[d] = v * v;
        __syncthreads();
        for (int s2 = 64; s2 > 0; s2 >>= 1) {
            if (d < s2) red[d] += red[d + s2];
            __syncthreads();
        }
        float nrm = __fsqrt_rn(red[0]);
        __syncthreads();
        float val = 0.5f * __fdiv_rn(v, fmaxf(nrm, 1e-12f));
        __half hi = __float2half_rn(val);
        float rr  = val - __half2float(hi);
        __half lo = __float2half_rn(rr * 2048.0f);
        dhi[(size_t)r * KDIM + c * DD + d] = hi;
        dlo[(size_t)r * KDIM + c * DD + d] = lo;
    }
}

// ---------------- K3: 3-pass FP16 split GEMM  S = A(4096x512) * B(4096x512)^T ----------------
// S = Ahi*Bhi + (Ahi*Blo + Alo*Bhi)/2048 ; 128x128 CTA tile, 16 warps, warp tile 32x32,
// k-chunk 32 (2 x k16 mma steps), double-buffered cp.async, ldmatrix fragment loads.
__global__ void __launch_bounds__(GT, 1) k_gemm() {
    extern __shared__ __align__(128) __half smh[];
    uint32_t sb;
    asm("{ .reg .u64 t; cvta.to.shared.u64 t, %1; cvt.u32.u64 %0, t; }"
        : "=r"(sb) : "l"(smh));
    const int tid = threadIdx.x;
    const int wid = tid >> 5, lane = tid & 31;
    const int g = lane >> 2, t = lane & 3;
    const int wm = wid >> 2, wn = wid & 3;
    const int bm = blockIdx.y * MT, bn = blockIdx.x * NT;

    float accH[2][4][4], accX[2][4][4];
#pragma unroll
    for (int mt = 0; mt < 2; mt++)
#pragma unroll
        for (int nt = 0; nt < 4; nt++)
#pragma unroll
            for (int r = 0; r < 4; r++) { accH[mt][nt][r] = 0.0f; accX[mt][nt][r] = 0.0f; }

    const int aRow = wm * 32 + (lane & 15);
    const int aK   = (lane >> 4) * 8;
    const uint32_t aOff0 = (uint32_t)((aRow)      * LDKH + aK) * 2;
    const uint32_t aOff1 = (uint32_t)((aRow + 16) * LDKH + aK) * 2;
    const int bRow = wn * 32 + (lane & 7) + ((lane >> 4) & 1) * 8;
    const int bK   = ((lane >> 3) & 1) * 8;
    const uint32_t bOff0 = (uint32_t)((bRow)      * LDKH + bK) * 2;
    const uint32_t bOff1 = (uint32_t)((bRow + 16) * LDKH + bK) * 2;

    auto load_chunk = [&](int kt, int stage) {
        uint32_t base = sb + (uint32_t)stage * (STAGE_H * 2);
        int row = tid >> 2, seg = tid & 3;
        uint32_t so = (uint32_t)(row * (LDKH * 2) + seg * 16);
        size_t goA = (size_t)(bm + row) * KDIM + kt * KCH + seg * 8;
        size_t goB = (size_t)(bn + row) * KDIM + kt * KCH + seg * 8;
        cpa16(base + so,                   g_Ahi + goA);
        cpa16(base + PLANE_H * 2     + so, g_Alo + goA);
        cpa16(base + PLANE_H * 4     + so, g_Bhi + goB);
        cpa16(base + PLANE_H * 6     + so, g_Blo + goB);
        asm volatile("cp.async.commit_group;" ::: "memory");
    };

    load_chunk(0, 0);

    for (int kt = 0; kt < NCHUNK; kt++) {
        int buf = kt & 1;
        if (kt + 1 < NCHUNK) {
            load_chunk(kt + 1, buf ^ 1);
            asm volatile("cp.async.wait_group 1;" ::: "memory");
        } else {
            asm volatile("cp.async.wait_group 0;" ::: "memory");
        }
        __syncthreads();

        uint32_t stg = sb + (uint32_t)buf * (STAGE_H * 2);

#pragma unroll
        for (int ks = 0; ks < 2; ks++) {
            const uint32_t kboff = (uint32_t)ks * 32;   // 16 halves = 32 bytes
            uint32_t bh[4][2], bl[4][2];
            ldsm4(bh[0][0], bh[0][1], bh[1][0], bh[1][1], stg + PLANE_H * 4 + bOff0 + kboff);
            ldsm4(bh[2][0], bh[2][1], bh[3][0], bh[3][1], stg + PLANE_H * 4 + bOff1 + kboff);
            ldsm4(bl[0][0], bl[0][1], bl[1][0], bl[1][1], stg + PLANE_H * 6 + bOff0 + kboff);
            ldsm4(bl[2][0], bl[2][1], bl[3][0], bl[3][1], stg + PLANE_H * 6 + bOff1 + kboff);
#pragma unroll
            for (int mt = 0; mt < 2; mt++) {
                uint32_t aoff = (mt == 0) ? aOff0 : aOff1;
                uint32_t ah0, ah1, ah2, ah3, al0, al1, al2, al3;
                ldsm4(ah0, ah1, ah2, ah3, stg +               aoff + kboff);
                ldsm4(al0, al1, al2, al3, stg + PLANE_H * 2 + aoff + kboff);
#pragma unroll
                for (int nt = 0; nt < 4; nt++) {
                    mma16(accH[mt][nt], ah0, ah1, ah2, ah3, bh[nt][0], bh[nt][1]);
                    mma16(accX[mt][nt], ah0, ah1, ah2, ah3, bl[nt][0], bl[nt][1]);
                    mma16(accX[mt][nt], al0, al1, al2, al3, bh[nt][0], bh[nt][1]);
                }
            }
        }
        __syncthreads();
    }

    const float IS = 1.0f / 2048.0f;
#pragma unroll
    for (int mt = 0; mt < 2; mt++) {
        int r0 = bm + wm * 32 + mt * 16 + g;
#pragma unroll
        for (int nt = 0; nt < 4; nt++) {
            int c = bn + wn * 32 + nt * 8 + 2 * t;
            float v0 = fmaf(accX[mt][nt][0], IS, accH[mt][nt][0]);
            float v1 = fmaf(accX[mt][nt][1], IS, accH[mt][nt][1]);
            float v2 = fmaf(accX[mt][nt][2], IS, accH[mt][nt][2]);
            float v3 = fmaf(accX[mt][nt][3], IS, accH[mt][nt][3]);
            *(float2*)(g_S + (size_t)r0 * MMm + c)       = make_float2(v0, v1);
            *(float2*)(g_S + (size_t)(r0 + 8) * MMm + c) = make_float2(v2, v3);
        }
    }
}

// ---------------- K4: mask existing incidences (dedup-safe) ----------------
__global__ void k_mask(const int* __restrict__ V, const int* __restrict__ E) {
    int i = blockIdx.x * blockDim.x + threadIdx.x;
    if (i < NNZ) {
        atomicExch(&g_S[(size_t)V[i] * MMm + E[i]], -1e30f);
    }
}

// ---------------- K5: top-11-bit histogram (positive values only — threshold is in
// the positive tail; negative buckets contribute identically to every cum >= KADD) --
__global__ void k_hist() {
    __shared__ unsigned h[2048];
    for (int j = threadIdx.x; j < 2048; j += blockDim.x) h[j] = 0;
    __syncthreads();
    int i  = blockIdx.x * blockDim.x + threadIdx.x;
    int st = gridDim.x * blockDim.x;
    const float4* S4 = (const float4*)g_S;
    for (int j = i; j < NM / 4; j += st) {
        float4 s = S4[j];
        if (s.x > 0.0f) atomicAdd(&h[f2ord(s.x) >> 21], 1u);
        if (s.y > 0.0f) atomicAdd(&h[f2ord(s.y) >> 21], 1u);
        if (s.z > 0.0f) atomicAdd(&h[f2ord(s.z) >> 21], 1u);
        if (s.w > 0.0f) atomicAdd(&h[f2ord(s.w) >> 21], 1u);
    }
    __syncthreads();
    for (int j = threadIdx.x; j < 2048; j += blockDim.x)
        if (h[j]) atomicAdd(&g_hist[j], h[j]);
}

// ---------------- K6: find threshold bucket (1 block, 1024 thr) ----------------
__global__ void k_pick() {
    __shared__ unsigned c[2048];
    int t = threadIdx.x;
    c[t] = g_hist[t];
    c[t + 1024] = g_hist[t + 1024];
    __syncthreads();
    for (int off = 1; off < 2048; off <<= 1) {
        unsigned a0 = (t + off < 2048) ? c[t + off] : 0u;
        unsigned a1 = (t + 1024 + off < 2048) ? c[t + 1024 + off] : 0u;
        __syncthreads();
        c[t] += a0; c[t + 1024] += a1;
        __syncthreads();
    }
    for (int b = t; b < 2048; b += 1024) {
        unsigned cum = c[b], nxt = (b + 1 < 2048) ? c[b + 1] : 0u;
        if (cum >= (unsigned)KADD && nxt < (unsigned)KADD) {
            g_B1 = (unsigned)b;
            g_r1 = (unsigned)KADD - nxt;
        }
    }
}

// ---------------- K7: collect candidates (ballot-aggregated global counter) ----------------
__global__ void k_collect() {
    unsigned B1 = g_B1;
    int lane = threadIdx.x & 31;
    int i  = blockIdx.x * blockDim.x + threadIdx.x;
    int st = gridDim.x * blockDim.x;
    const float4* S4 = (const float4*)g_S;
    // NM/4 = 4194304 is an exact multiple of st (524288): uniform 8 iterations/thread,
    // so warp-synchronous ballots are safe.
    for (int j = i; j < NM / 4; j += st) {
        float4 s = S4[j];
        unsigned u[4] = { f2ord(s.x), f2ord(s.y), f2ord(s.z), f2ord(s.w) };
#pragma unroll
        for (int q = 0; q < 4; q++) {
            bool pred = (u[q] >> 21) == B1;
            unsigned m = __ballot_sync(0xFFFFFFFFu, pred);
            if (m) {
                int leader = __ffs(m) - 1;
                unsigned base = 0;
                if (lane == leader) base = atomicAdd(&g_candCount, (unsigned)__popc(m));
                base = __shfl_sync(0xFFFFFFFFu, base, leader);
                unsigned rank = __popc(m & ((1u << lane) - 1u));
                if (pred && base + rank < CAPC) g_cand[base + rank] = u[q];
            }
        }
    }
}

// ---------------- K8: exact k-th value via 11+10 bit refine (1 block) ----------------
__global__ void k_select() {
    __shared__ unsigned h[2048];
    __shared__ unsigned sb2, sr2;
    int t = threadIdx.x;  // 1024
    unsigned nc = g_candCount; if (nc > CAPC) nc = CAPC;
    unsigned r1 = g_r1;

    h[t] = 0; h[t + 1024] = 0;
    __syncthreads();
    for (unsigned i = t; i < nc; i += 1024)
        atomicAdd(&h[(g_cand[i] >> 10) & 2047u], 1u);
    __syncthreads();
    for (int off = 1; off < 2048; off <<= 1) {
        unsigned a0 = (t + off < 2048) ? h[t + off] : 0u;
        unsigned a1 = (t + 1024 + off < 2048) ? h[t + 1024 + off] : 0u;
        __syncthreads();
        h[t] += a0; h[t + 1024] += a1;
        __syncthreads();
    }
    for (int b = t; b < 2048; b += 1024) {
        unsigned cum = h[b], nxt = (b + 1 < 2048) ? h[b + 1] : 0u;
        if (cum >= r1 && nxt < r1) { sb2 = (unsigned)b; sr2 = r1 - nxt; }
    }
    __syncthreads();
    unsigned b2 = sb2, r2 = sr2;

    h[t] = 0;
    __syncthreads();
    for (unsigned i = t; i < nc; i += 1024) {
        unsigned u = g_cand[i];
        if (((u >> 10) & 2047u) == b2) atomicAdd(&h[u & 1023u], 1u);
    }
    __syncthreads();
    for (int off = 1; off < 1024; off <<= 1) {
        unsigned a = (t + off < 1024) ? h[t + off] : 0u;
        __syncthreads();
        h[t] += a;
        __syncthreads();
    }
    unsigned cum = h[t], nxt = (t + 1 < 1024) ? h[t + 1] : 0u;
    if (cum >= r2 && nxt < r2)
        g_Tbits = (g_B1 << 21) | (b2 << 10) | (unsigned)t;
}

// ---------------- K9: fused output ----------------
__device__ __forceinline__ float outval(float h, float p, float e, float s, unsigned T) {
    float enr = h + ((f2ord(s) >= T) ? 1.0f : 0.0f);
    float pa = __fadd_rn(p, 1e-8f);
    float pb = __fadd_rn(__fsub_rn(1.0f, p), 1e-8f);
    float eb = __fsub_rn(1.0f, e);
    double lhs = (double)e  * (double)pa;
    double rhs = (double)eb * (double)pb;
    return (lhs > rhs) ? enr : 0.0f;
}

__global__ void k_final(const float* __restrict__ H, const float* __restrict__ P,
                        const float* __restrict__ Eps, float* __restrict__ out) {
    unsigned T = g_Tbits;
    int i  = blockIdx.x * blockDim.x + threadIdx.x;
    int st = gridDim.x * blockDim.x;
    const float4* H4 = (const float4*)H;
    const float4* P4 = (const float4*)P;
    const float4* E4 = (const float4*)Eps;
    const float4* S4 = (const float4*)g_S;
    float4* O4 = (float4*)out;
    for (int j = i; j < NM / 4; j += st) {
        float4 h4 = H4[j], p4 = P4[j], e4 = E4[j], s4 = S4[j];
        float4 o;
        o.x = outval(h4.x, p4.x, e4.x, s4.x, T);
        o.y = outval(h4.y, p4.y, e4.y, s4.y, T);
        o.z = outval(h4.z, p4.z, e4.z, s4.z, T);
        o.w = outval(h4.w, p4.w, e4.w, s4.w, T);
        O4[j] = o;
    }
}

// ---------------- launch ----------------
extern "C" void kernel_launch(void* const* d_in, const int* in_sizes, int n_in,
                              void* d_out, int out_size) {
    const float* X   = (const float*)d_in[0];
    const float* H   = (const float*)d_in[1];
    const int*   V   = (const int*)d_in[2];
    const int*   E   = (const int*)d_in[3];
    const float* P   = (const float*)d_in[4];
    const float* W   = (const float*)d_in[5];
    const float* Eps = (const float*)d_in[6];
    float* out = (float*)d_out;

    cudaFuncSetAttribute(k_gemm, cudaFuncAttributeMaxDynamicSharedMemorySize, SMEM_BYTES);

    k_zero<<<64, 256>>>();
    k_count<<<NNZ / 256, 256>>>(E);
    k_prefix<<<1, 1024>>>();
    k_fill<<<NNZ / 256, 256>>>(V, E);
    {
        dim3 fg(NN, 2);
        k_feat<<<fg, 128>>>(X, W);
    }
    {
        dim3 gg(MMm / NT, NN / MT);   // (32, 32)
        k_gemm<<<gg, GT, SMEM_BYTES>>>();
    }
    k_mask<<<NNZ / 256, 256>>>(V, E);
    k_hist<<<2048, 256>>>();
    k_pick<<<1, 1024>>>();
    k_collect<<<2048, 256>>>();
    k_select<<<1, 1024>>>();
    k_final<<<4096, 256>>>(H, P, Eps, out);
}

// round 14
// speedup vs baseline: 1.6322x; 1.0063x over previous
#include <cuda_runtime.h>
#include <cuda_fp16.h>
#include <cstdint>

#define NN   4096
#define MMm  4096
#define DD   128
#define CC   4
#define NNZ  262144
#define KDIM 512
#define KADD 26214
#define NM   (NN * MMm)
#define CAPC (4u * 1024u * 1024u)

// GEMM tiling (mma.sync fp16 m16n8k16, 2-term split, 4-stage pipeline)
#define MT      128
#define NT      128
#define KCH     32
#define NCHUNK  (KDIM / KCH)          // 16
#define LDKH    40                    // padded k-stride in halves (32+8) -> conflict-free ldmatrix
#define PLANE_H (128 * LDKH)          // 5120 halves per plane
#define STAGE_H (4 * PLANE_H)         // 20480 halves per stage
#define NSTAGE  4
#define SMEM_BYTES (NSTAGE * STAGE_H * 2)  // 163840 bytes
#define GT      512                   // gemm threads

// ---------------- scratch (static device memory; no allocs allowed) ----------------
__device__ int       g_cnt[MMm];             // segment counts
__device__ unsigned  g_eoff[MMm + 1];        // CSR offsets
__device__ unsigned  g_ecur[MMm];            // fill cursors
__device__ int       g_eidx[NNZ];            // CSR node indices
__device__ __half    g_Ahi[NN * KDIM];       // node feature fp16 hi plane
__device__ __half    g_Alo[NN * KDIM];       // node feature fp16 lo*2048 plane
__device__ __half    g_Bhi[MMm * KDIM];      // edge feature fp16 hi plane
__device__ __half    g_Blo[MMm * KDIM];      // edge feature fp16 lo*2048 plane
__device__ float     g_S[NM];                // similarity matrix (masked)
__device__ unsigned  g_hist[2048];
__device__ unsigned  g_cand[CAPC];
__device__ unsigned  g_candCount;
__device__ unsigned  g_B1;
__device__ unsigned  g_r1;
__device__ unsigned  g_Tbits;

__device__ __forceinline__ unsigned f2ord(float f) {
    unsigned u = __float_as_uint(f);
    return (u & 0x80000000u) ? ~u : (u | 0x80000000u);
}
__device__ __forceinline__ void cpa16(uint32_t dst, const void* src) {
    asm volatile("cp.async.cg.shared.global [%0], [%1], 16;"
                 :: "r"(dst), "l"(__cvta_generic_to_global(src)) : "memory");
}
// m16n8k16 fp16 mma: D = A*B + D  (row.col), fp32 accumulate
__device__ __forceinline__ void mma16(float* c,
                                      uint32_t a0, uint32_t a1, uint32_t a2, uint32_t a3,
                                      uint32_t b0, uint32_t b1) {
    asm volatile(
        "mma.sync.aligned.m16n8k16.row.col.f32.f16.f16.f32 "
        "{%0,%1,%2,%3}, {%4,%5,%6,%7}, {%8,%9}, {%0,%1,%2,%3};"
        : "+f"(c[0]), "+f"(c[1]), "+f"(c[2]), "+f"(c[3])
        : "r"(a0), "r"(a1), "r"(a2), "r"(a3), "r"(b0), "r"(b1));
}
__device__ __forceinline__ void ldsm4(uint32_t& r0, uint32_t& r1, uint32_t& r2, uint32_t& r3,
                                      uint32_t addr) {
    asm volatile("ldmatrix.sync.aligned.m8n8.x4.shared.b16 {%0,%1,%2,%3}, [%4];"
                 : "=r"(r0), "=r"(r1), "=r"(r2), "=r"(r3) : "r"(addr));
}

// ---------------- K0: zero transient state (runs every replay) ----------------
__global__ void k_zero() {
    int i  = blockIdx.x * blockDim.x + threadIdx.x;
    int st = gridDim.x * blockDim.x;
    for (int j = i; j < MMm;  j += st) { g_cnt[j] = 0; g_ecur[j] = 0; }
    for (int j = i; j < 2048; j += st) g_hist[j] = 0;
    if (i == 0) g_candCount = 0;
}

// ---------------- CSR build: count -> prefix -> fill ----------------
__global__ void k_count(const int* __restrict__ E) {
    int i = blockIdx.x * blockDim.x + threadIdx.x;
    if (i < NNZ) atomicAdd(&g_cnt[E[i]], 1);
}

__global__ void k_prefix() {   // exclusive prefix of g_cnt into g_eoff (1 block, 1024 thr)
    __shared__ unsigned s[1024];
    int t = threadIdx.x;
    unsigned c0 = g_cnt[4*t], c1 = g_cnt[4*t+1], c2 = g_cnt[4*t+2], c3 = g_cnt[4*t+3];
    s[t] = c0 + c1 + c2 + c3;
    __syncthreads();
    for (int off = 1; off < 1024; off <<= 1) {
        unsigned v = (t >= off) ? s[t - off] : 0u;
        __syncthreads();
        s[t] += v;
        __syncthreads();
    }
    unsigned base = t ? s[t-1] : 0u;
    g_eoff[4*t]   = base;
    g_eoff[4*t+1] = base + c0;
    g_eoff[4*t+2] = base + c0 + c1;
    g_eoff[4*t+3] = base + c0 + c1 + c2;
    if (t == 1023) g_eoff[MMm] = s[1023];
}

__global__ void k_fill(const int* __restrict__ V, const int* __restrict__ E) {
    int i = blockIdx.x * blockDim.x + threadIdx.x;
    if (i < NNZ) {
        int e = E[i];
        unsigned pos = atomicAdd(&g_ecur[e], 1u);
        g_eidx[g_eoff[e] + pos] = V[i];
    }
}

// ---------------- K2: build 0.5 * l2norm(x * w_c) features, fp16 hi/lo planes ----------------
// Edge gather unrolled x4 (independent int64 accumulators; integer adds exact/associative).
__global__ void k_feat(const float* __restrict__ X, const float* __restrict__ W) {
    int r   = blockIdx.x;
    int isE = blockIdx.y;
    int d   = threadIdx.x;   // 128 threads
    __shared__ float red[128];
    float x;
    if (!isE) {
        x = X[(size_t)r * DD + d];
    } else {
        unsigned s0 = g_eoff[r], s1 = g_eoff[r + 1];
        long long a0 = 0, a1 = 0, a2 = 0, a3 = 0;
        unsigned j = s0;
        for (; j + 4 <= s1; j += 4) {
            int v0 = g_eidx[j], v1 = g_eidx[j+1], v2 = g_eidx[j+2], v3 = g_eidx[j+3];
            a0 += __double2ll_rn((double)X[(size_t)v0 * DD + d] * 4294967296.0);
            a1 += __double2ll_rn((double)X[(size_t)v1 * DD + d] * 4294967296.0);
            a2 += __double2ll_rn((double)X[(size_t)v2 * DD + d] * 4294967296.0);
            a3 += __double2ll_rn((double)X[(size_t)v3 * DD + d] * 4294967296.0);
        }
        for (; j < s1; j++)
            a0 += __double2ll_rn((double)X[(size_t)g_eidx[j] * DD + d] * 4294967296.0);
        long long acc = a0 + a1 + a2 + a3;
        float cnt = (float)(s1 - s0);
        float sum = (float)((double)acc * (1.0 / 4294967296.0));
        x = __fdiv_rn(sum, fmaxf(cnt, 1.0f));
    }
    __half* dhi = isE ? g_Bhi : g_Ahi;
    __half* dlo = isE ? g_Blo : g_Alo;
#pragma unroll
    for (int c = 0; c < CC; c++) {
        float v = x * W[c * DD + d];
        red[d] = v * v;
        __syncthreads();
        for (int s2 = 64; s2 > 0; s2 >>= 1) {
            if (d < s2) red[d] += red[d + s2];
            __syncthreads();
        }
        float nrm = __fsqrt_rn(red[0]);
        __syncthreads();
        float val = 0.5f * __fdiv_rn(v, fmaxf(nrm, 1e-12f));
        __half hi = __float2half_rn(val);
        float rr  = val - __half2float(hi);
        __half lo = __float2half_rn(rr * 2048.0f);
        dhi[(size_t)r * KDIM + c * DD + d] = hi;
        dlo[(size_t)r * KDIM + c * DD + d] = lo;
    }
}

// ---------------- K3: 3-pass FP16 split GEMM  S = A(4096x512) * B(4096x512)^T ----------------
// S = Ahi*Bhi + (Ahi*Blo + Alo*Bhi)/2048 ; 128x128 CTA tile, 16 warps, warp tile 32x32,
// k-chunk 32 (2 x k16 mma steps), 4-stage cp.async pipeline (3 chunks in flight), ldmatrix.
__global__ void __launch_bounds__(GT, 1) k_gemm() {
    extern __shared__ __align__(128) __half smh[];
    uint32_t sb;
    asm("{ .reg .u64 t; cvta.to.shared.u64 t, %1; cvt.u32.u64 %0, t; }"
        : "=r"(sb) : "l"(smh));
    const int tid = threadIdx.x;
    const int wid = tid >> 5, lane = tid & 31;
    const int g = lane >> 2, t = lane & 3;
    const int wm = wid >> 2, wn = wid & 3;
    const int bm = blockIdx.y * MT, bn = blockIdx.x * NT;

    float accH[2][4][4], accX[2][4][4];
#pragma unroll
    for (int mt = 0; mt < 2; mt++)
#pragma unroll
        for (int nt = 0; nt < 4; nt++)
#pragma unroll
            for (int r = 0; r < 4; r++) { accH[mt][nt][r] = 0.0f; accX[mt][nt][r] = 0.0f; }

    const int aRow = wm * 32 + (lane & 15);
    const int aK   = (lane >> 4) * 8;
    const uint32_t aOff0 = (uint32_t)((aRow)      * LDKH + aK) * 2;
    const uint32_t aOff1 = (uint32_t)((aRow + 16) * LDKH + aK) * 2;
    const int bRow = wn * 32 + (lane & 7) + ((lane >> 4) & 1) * 8;
    const int bK   = ((lane >> 3) & 1) * 8;
    const uint32_t bOff0 = (uint32_t)((bRow)      * LDKH + bK) * 2;
    const uint32_t bOff1 = (uint32_t)((bRow + 16) * LDKH + bK) * 2;

    auto load_chunk = [&](int kt, int stage) {
        uint32_t base = sb + (uint32_t)stage * (STAGE_H * 2);
        int row = tid >> 2, seg = tid & 3;
        uint32_t so = (uint32_t)(row * (LDKH * 2) + seg * 16);
        size_t goA = (size_t)(bm + row) * KDIM + kt * KCH + seg * 8;
        size_t goB = (size_t)(bn + row) * KDIM + kt * KCH + seg * 8;
        cpa16(base + so,                   g_Ahi + goA);
        cpa16(base + PLANE_H * 2     + so, g_Alo + goA);
        cpa16(base + PLANE_H * 4     + so, g_Bhi + goB);
        cpa16(base + PLANE_H * 6     + so, g_Blo + goB);
        asm volatile("cp.async.commit_group;" ::: "memory");
    };

    // prologue: fill 3 of 4 stages
    load_chunk(0, 0);
    load_chunk(1, 1);
    load_chunk(2, 2);

    for (int kt = 0; kt < NCHUNK; kt++) {
        // drain chunk kt (leave min(2, 15-kt) groups outstanding)
        if (kt <= 13)      asm volatile("cp.async.wait_group 2;" ::: "memory");
        else if (kt == 14) asm volatile("cp.async.wait_group 1;" ::: "memory");
        else               asm volatile("cp.async.wait_group 0;" ::: "memory");
        __syncthreads();   // all threads' chunk-kt data visible; all done computing kt-1

        if (kt + 3 < NCHUNK) load_chunk(kt + 3, (kt + 3) & (NSTAGE - 1));

        uint32_t stg = sb + (uint32_t)(kt & (NSTAGE - 1)) * (STAGE_H * 2);

#pragma unroll
        for (int ks = 0; ks < 2; ks++) {
            const uint32_t kboff = (uint32_t)ks * 32;   // 16 halves = 32 bytes
            uint32_t bh[4][2], bl[4][2];
            ldsm4(bh[0][0], bh[0][1], bh[1][0], bh[1][1], stg + PLANE_H * 4 + bOff0 + kboff);
            ldsm4(bh[2][0], bh[2][1], bh[3][0], bh[3][1], stg + PLANE_H * 4 + bOff1 + kboff);
            ldsm4(bl[0][0], bl[0][1], bl[1][0], bl[1][1], stg + PLANE_H * 6 + bOff0 + kboff);
            ldsm4(bl[2][0], bl[2][1], bl[3][0], bl[3][1], stg + PLANE_H * 6 + bOff1 + kboff);
#pragma unroll
            for (int mt = 0; mt < 2; mt++) {
                uint32_t aoff = (mt == 0) ? aOff0 : aOff1;
                uint32_t ah0, ah1, ah2, ah3, al0, al1, al2, al3;
                ldsm4(ah0, ah1, ah2, ah3, stg +               aoff + kboff);
                ldsm4(al0, al1, al2, al3, stg + PLANE_H * 2 + aoff + kboff);
#pragma unroll
                for (int nt = 0; nt < 4; nt++) {
                    mma16(accH[mt][nt], ah0, ah1, ah2, ah3, bh[nt][0], bh[nt][1]);
                    mma16(accX[mt][nt], ah0, ah1, ah2, ah3, bl[nt][0], bl[nt][1]);
                    mma16(accX[mt][nt], al0, al1, al2, al3, bh[nt][0], bh[nt][1]);
                }
            }
        }
    }

    __syncthreads();
    const float IS = 1.0f / 2048.0f;
#pragma unroll
    for (int mt = 0; mt < 2; mt++) {
        int r0 = bm + wm * 32 + mt * 16 + g;
#pragma unroll
        for (int nt = 0; nt < 4; nt++) {
            int c = bn + wn * 32 + nt * 8 + 2 * t;
            float v0 = fmaf(accX[mt][nt][0], IS, accH[mt][nt][0]);
            float v1 = fmaf(accX[mt][nt][1], IS, accH[mt][nt][1]);
            float v2 = fmaf(accX[mt][nt][2], IS, accH[mt][nt][2]);
            float v3 = fmaf(accX[mt][nt][3], IS, accH[mt][nt][3]);
            *(float2*)(g_S + (size_t)r0 * MMm + c)       = make_float2(v0, v1);
            *(float2*)(g_S + (size_t)(r0 + 8) * MMm + c) = make_float2(v2, v3);
        }
    }
}

// ---------------- K4: mask existing incidences (dedup-safe) ----------------
__global__ void k_mask(const int* __restrict__ V, const int* __restrict__ E) {
    int i = blockIdx.x * blockDim.x + threadIdx.x;
    if (i < NNZ) {
        atomicExch(&g_S[(size_t)V[i] * MMm + E[i]], -1e30f);
    }
}

// ---------------- K5: top-11-bit histogram (positive values only) ----------------
__global__ void k_hist() {
    __shared__ unsigned h[2048];
    for (int j = threadIdx.x; j < 2048; j += blockDim.x) h[j] = 0;
    __syncthreads();
    int i  = blockIdx.x * blockDim.x + threadIdx.x;
    int st = gridDim.x * blockDim.x;
    const float4* S4 = (const float4*)g_S;
    for (int j = i; j < NM / 4; j += st) {
        float4 s = S4[j];
        if (s.x > 0.0f) atomicAdd(&h[f2ord(s.x) >> 21], 1u);
        if (s.y > 0.0f) atomicAdd(&h[f2ord(s.y) >> 21], 1u);
        if (s.z > 0.0f) atomicAdd(&h[f2ord(s.z) >> 21], 1u);
        if (s.w > 0.0f) atomicAdd(&h[f2ord(s.w) >> 21], 1u);
    }
    __syncthreads();
    for (int j = threadIdx.x; j < 2048; j += blockDim.x)
        if (h[j]) atomicAdd(&g_hist[j], h[j]);
}

// ---------------- K6: find threshold bucket (1 block, 1024 thr) ----------------
__global__ void k_pick() {
    __shared__ unsigned c[2048];
    int t = threadIdx.x;
    c[t] = g_hist[t];
    c[t + 1024] = g_hist[t + 1024];
    __syncthreads();
    for (int off = 1; off < 2048; off <<= 1) {
        unsigned a0 = (t + off < 2048) ? c[t + off] : 0u;
        unsigned a1 = (t + 1024 + off < 2048) ? c[t + 1024 + off] : 0u;
        __syncthreads();
        c[t] += a0; c[t + 1024] += a1;
        __syncthreads();
    }
    for (int b = t; b < 2048; b += 1024) {
        unsigned cum = c[b], nxt = (b + 1 < 2048) ? c[b + 1] : 0u;
        if (cum >= (unsigned)KADD && nxt < (unsigned)KADD) {
            g_B1 = (unsigned)b;
            g_r1 = (unsigned)KADD - nxt;
        }
    }
}

// ---------------- K7: collect candidates (ballot-aggregated global counter) ----------------
__global__ void k_collect() {
    unsigned B1 = g_B1;
    int lane = threadIdx.x & 31;
    int i  = blockIdx.x * blockDim.x + threadIdx.x;
    int st = gridDim.x * blockDim.x;
    const float4* S4 = (const float4*)g_S;
    for (int j = i; j < NM / 4; j += st) {
        float4 s = S4[j];
        unsigned u[4] = { f2ord(s.x), f2ord(s.y), f2ord(s.z), f2ord(s.w) };
#pragma unroll
        for (int q = 0; q < 4; q++) {
            bool pred = (u[q] >> 21) == B1;
            unsigned m = __ballot_sync(0xFFFFFFFFu, pred);
            if (m) {
                int leader = __ffs(m) - 1;
                unsigned base = 0;
                if (lane == leader) base = atomicAdd(&g_candCount, (unsigned)__popc(m));
                base = __shfl_sync(0xFFFFFFFFu, base, leader);
                unsigned rank = __popc(m & ((1u << lane) - 1u));
                if (pred && base + rank < CAPC) g_cand[base + rank] = u[q];
            }
        }
    }
}

// ---------------- K8: exact k-th value via 11+10 bit refine (1 block) ----------------
__global__ void k_select() {
    __shared__ unsigned h[2048];
    __shared__ unsigned sb2, sr2;
    int t = threadIdx.x;  // 1024
    unsigned nc = g_candCount; if (nc > CAPC) nc = CAPC;
    unsigned r1 = g_r1;

    h[t] = 0; h[t + 1024] = 0;
    __syncthreads();
    for (unsigned i = t; i < nc; i += 1024)
        atomicAdd(&h[(g_cand[i] >> 10) & 2047u], 1u);
    __syncthreads();
    for (int off = 1; off < 2048; off <<= 1) {
        unsigned a0 = (t + off < 2048) ? h[t + off] : 0u;
        unsigned a1 = (t + 1024 + off < 2048) ? h[t + 1024 + off] : 0u;
        __syncthreads();
        h[t] += a0; h[t + 1024] += a1;
        __syncthreads();
    }
    for (int b = t; b < 2048; b += 1024) {
        unsigned cum = h[b], nxt = (b + 1 < 2048) ? h[b + 1] : 0u;
        if (cum >= r1 && nxt < r1) { sb2 = (unsigned)b; sr2 = r1 - nxt; }
    }
    __syncthreads();
    unsigned b2 = sb2, r2 = sr2;

    h[t] = 0;
    __syncthreads();
    for (unsigned i = t; i < nc; i += 1024) {
        unsigned u = g_cand[i];
        if (((u >> 10) & 2047u) == b2) atomicAdd(&h[u & 1023u], 1u);
    }
    __syncthreads();
    for (int off = 1; off < 1024; off <<= 1) {
        unsigned a = (t + off < 1024) ? h[t + off] : 0u;
        __syncthreads();
        h[t] += a;
        __syncthreads();
    }
    unsigned cum = h[t], nxt = (t + 1 < 1024) ? h[t + 1] : 0u;
    if (cum >= r2 && nxt < r2)
        g_Tbits = (g_B1 << 21) | (b2 << 10) | (unsigned)t;
}

// ---------------- K9: fused output ----------------
__device__ __forceinline__ float outval(float h, float p, float e, float s, unsigned T) {
    float enr = h + ((f2ord(s) >= T) ? 1.0f : 0.0f);
    float pa = __fadd_rn(p, 1e-8f);
    float pb = __fadd_rn(__fsub_rn(1.0f, p), 1e-8f);
    float eb = __fsub_rn(1.0f, e);
    double lhs = (double)e  * (double)pa;
    double rhs = (double)eb * (double)pb;
    return (lhs > rhs) ? enr : 0.0f;
}

__global__ void k_final(const float* __restrict__ H, const float* __restrict__ P,
                        const float* __restrict__ Eps, float* __restrict__ out) {
    unsigned T = g_Tbits;
    int i  = blockIdx.x * blockDim.x + threadIdx.x;
    int st = gridDim.x * blockDim.x;
    const float4* H4 = (const float4*)H;
    const float4* P4 = (const float4*)P;
    const float4* E4 = (const float4*)Eps;
    const float4* S4 = (const float4*)g_S;
    float4* O4 = (float4*)out;
    for (int j = i; j < NM / 4; j += st) {
        float4 h4 = H4[j], p4 = P4[j], e4 = E4[j], s4 = S4[j];
        float4 o;
        o.x = outval(h4.x, p4.x, e4.x, s4.x, T);
        o.y = outval(h4.y, p4.y, e4.y, s4.y, T);
        o.z = outval(h4.z, p4.z, e4.z, s4.z, T);
        o.w = outval(h4.w, p4.w, e4.w, s4.w, T);
        O4[j] = o;
    }
}

// ---------------- launch ----------------
extern "C" void kernel_launch(void* const* d_in, const int* in_sizes, int n_in,
                              void* d_out, int out_size) {
    const float* X   = (const float*)d_in[0];
    const float* H   = (const float*)d_in[1];
    const int*   V   = (const int*)d_in[2];
    const int*   E   = (const int*)d_in[3];
    const float* P   = (const float*)d_in[4];
    const float* W   = (const float*)d_in[5];
    const float* Eps = (const float*)d_in[6];
    float* out = (float*)d_out;

    cudaFuncSetAttribute(k_gemm, cudaFuncAttributeMaxDynamicSharedMemorySize, SMEM_BYTES);

    k_zero<<<64, 256>>>();
    k_count<<<NNZ / 256, 256>>>(E);
    k_prefix<<<1, 1024>>>();
    k_fill<<<NNZ / 256, 256>>>(V, E);
    {
        dim3 fg(NN, 2);
        k_feat<<<fg, 128>>>(X, W);
    }
    {
        dim3 gg(MMm / NT, NN / MT);   // (32, 32)
        k_gemm<<<gg, GT, SMEM_BYTES>>>();
    }
    k_mask<<<NNZ / 256, 256>>>(V, E);
    k_hist<<<2048, 256>>>();
    k_pick<<<1, 1024>>>();
    k_collect<<<2048, 256>>>();
    k_select<<<1, 1024>>>();
    k_final<<<4096, 256>>>(H, P, Eps, out);
}

// round 15
// speedup vs baseline: 1.7000x; 1.0415x over previous
#include <cuda_runtime.h>
#include <cuda_fp16.h>
#include <cstdint>

#define NN   4096
#define MMm  4096
#define DD   128
#define CC   4
#define NNZ  262144
#define KDIM 512
#define KADD 26214
#define NM   (NN * MMm)
#define CAPC (4u * 1024u * 1024u)

// GEMM tiling (mma.sync fp16 m16n8k16, 2-term split, 4-stage pipeline)
#define MT      128
#define NT      128
#define KCH     32
#define NCHUNK  (KDIM / KCH)          // 16
#define LDKH    40                    // padded k-stride in halves (32+8) -> conflict-free ldmatrix
#define PLANE_H (128 * LDKH)          // 5120 halves per plane
#define STAGE_H (4 * PLANE_H)         // 20480 halves per stage
#define NSTAGE  4
#define SMEM_BYTES (NSTAGE * STAGE_H * 2)  // 163840 bytes
#define GT      512                   // gemm threads

// ---------------- scratch (static device memory; no allocs allowed) ----------------
__device__ int       g_cnt[MMm];             // segment counts
__device__ unsigned  g_eoff[MMm + 1];        // CSR offsets
__device__ unsigned  g_ecur[MMm];            // fill cursors
__device__ int       g_eidx[NNZ];            // CSR node indices
__device__ __half    g_Ahi[NN * KDIM];       // node feature fp16 hi plane
__device__ __half    g_Alo[NN * KDIM];       // node feature fp16 lo*2048 plane
__device__ __half    g_Bhi[MMm * KDIM];      // edge feature fp16 hi plane
__device__ __half    g_Blo[MMm * KDIM];      // edge feature fp16 lo*2048 plane
__device__ float     g_S[NM];                // similarity matrix (masked)
__device__ unsigned  g_hist[2048];
__device__ unsigned  g_cand[CAPC];           // candidate ordered-uints (bucket >= B1)
__device__ unsigned  g_cidx[CAPC];           // candidate flat indices
__device__ unsigned  g_candCount;
__device__ unsigned  g_B1;
__device__ unsigned  g_Tbits;                // exact KADD-th largest value (ordered bits)

__device__ __forceinline__ unsigned f2ord(float f) {
    unsigned u = __float_as_uint(f);
    return (u & 0x80000000u) ? ~u : (u | 0x80000000u);
}
__device__ __forceinline__ void cpa16(uint32_t dst, const void* src) {
    asm volatile("cp.async.cg.shared.global [%0], [%1], 16;"
                 :: "r"(dst), "l"(__cvta_generic_to_global(src)) : "memory");
}
// m16n8k16 fp16 mma: D = A*B + D  (row.col), fp32 accumulate
__device__ __forceinline__ void mma16(float* c,
                                      uint32_t a0, uint32_t a1, uint32_t a2, uint32_t a3,
                                      uint32_t b0, uint32_t b1) {
    asm volatile(
        "mma.sync.aligned.m16n8k16.row.col.f32.f16.f16.f32 "
        "{%0,%1,%2,%3}, {%4,%5,%6,%7}, {%8,%9}, {%0,%1,%2,%3};"
        : "+f"(c[0]), "+f"(c[1]), "+f"(c[2]), "+f"(c[3])
        : "r"(a0), "r"(a1), "r"(a2), "r"(a3), "r"(b0), "r"(b1));
}
__device__ __forceinline__ void ldsm4(uint32_t& r0, uint32_t& r1, uint32_t& r2, uint32_t& r3,
                                      uint32_t addr) {
    asm volatile("ldmatrix.sync.aligned.m8n8.x4.shared.b16 {%0,%1,%2,%3}, [%4];"
                 : "=r"(r0), "=r"(r1), "=r"(r2), "=r"(r3) : "r"(addr));
}
// exact gumbel-sigmoid hard mask: sign(e*(p+1e-8) - (1-e)*((1-p)+1e-8)) in fp64
__device__ __forceinline__ bool hardmask(float p, float e) {
    float pa = __fadd_rn(p, 1e-8f);
    float pb = __fadd_rn(__fsub_rn(1.0f, p), 1e-8f);
    float eb = __fsub_rn(1.0f, e);
    return (double)e * (double)pa > (double)eb * (double)pb;
}

// ---------------- K0: zero transient state (runs every replay) ----------------
__global__ void k_zero() {
    int i  = blockIdx.x * blockDim.x + threadIdx.x;
    int st = gridDim.x * blockDim.x;
    for (int j = i; j < MMm;  j += st) { g_cnt[j] = 0; g_ecur[j] = 0; }
    for (int j = i; j < 2048; j += st) g_hist[j] = 0;
    if (i == 0) g_candCount = 0;
}

// ---------------- K-zout: zero the output buffer (poisoned each replay) ----------------
__global__ void k_zout(float* __restrict__ out) {
    int i = blockIdx.x * blockDim.x + threadIdx.x;
    ((float4*)out)[i] = make_float4(0.0f, 0.0f, 0.0f, 0.0f);
}

// ---------------- CSR build: count -> prefix -> fill ----------------
__global__ void k_count(const int* __restrict__ E) {
    int i = blockIdx.x * blockDim.x + threadIdx.x;
    if (i < NNZ) atomicAdd(&g_cnt[E[i]], 1);
}

__global__ void k_prefix() {   // exclusive prefix of g_cnt into g_eoff (1 block, 1024 thr)
    __shared__ unsigned s[1024];
    int t = threadIdx.x;
    unsigned c0 = g_cnt[4*t], c1 = g_cnt[4*t+1], c2 = g_cnt[4*t+2], c3 = g_cnt[4*t+3];
    s[t] = c0 + c1 + c2 + c3;
    __syncthreads();
    for (int off = 1; off < 1024; off <<= 1) {
        unsigned v = (t >= off) ? s[t - off] : 0u;
        __syncthreads();
        s[t] += v;
        __syncthreads();
    }
    unsigned base = t ? s[t-1] : 0u;
    g_eoff[4*t]   = base;
    g_eoff[4*t+1] = base + c0;
    g_eoff[4*t+2] = base + c0 + c1;
    g_eoff[4*t+3] = base + c0 + c1 + c2;
    if (t == 1023) g_eoff[MMm] = s[1023];
}

__global__ void k_fill(const int* __restrict__ V, const int* __restrict__ E) {
    int i = blockIdx.x * blockDim.x + threadIdx.x;
    if (i < NNZ) {
        int e = E[i];
        unsigned pos = atomicAdd(&g_ecur[e], 1u);
        g_eidx[g_eoff[e] + pos] = V[i];
    }
}

// ---------------- K2: build 0.5 * l2norm(x * w_c) features, fp16 hi/lo planes ----------------
__global__ void k_feat(const float* __restrict__ X, const float* __restrict__ W) {
    int r   = blockIdx.x;
    int isE = blockIdx.y;
    int d   = threadIdx.x;   // 128 threads
    __shared__ float red[128];
    float x;
    if (!isE) {
        x = X[(size_t)r * DD + d];
    } else {
        unsigned s0 = g_eoff[r], s1 = g_eoff[r + 1];
        long long a0 = 0, a1 = 0, a2 = 0, a3 = 0;
        unsigned j = s0;
        for (; j + 4 <= s1; j += 4) {
            int v0 = g_eidx[j], v1 = g_eidx[j+1], v2 = g_eidx[j+2], v3 = g_eidx[j+3];
            a0 += __double2ll_rn((double)X[(size_t)v0 * DD + d] * 4294967296.0);
            a1 += __double2ll_rn((double)X[(size_t)v1 * DD + d] * 4294967296.0);
            a2 += __double2ll_rn((double)X[(size_t)v2 * DD + d] * 4294967296.0);
            a3 += __double2ll_rn((double)X[(size_t)v3 * DD + d] * 4294967296.0);
        }
        for (; j < s1; j++)
            a0 += __double2ll_rn((double)X[(size_t)g_eidx[j] * DD + d] * 4294967296.0);
        long long acc = a0 + a1 + a2 + a3;
        float cnt = (float)(s1 - s0);
        float sum = (float)((double)acc * (1.0 / 4294967296.0));
        x = __fdiv_rn(sum, fmaxf(cnt, 1.0f));
    }
    __half* dhi = isE ? g_Bhi : g_Ahi;
    __half* dlo = isE ? g_Blo : g_Alo;
#pragma unroll
    for (int c = 0; c < CC; c++) {
        float v = x * W[c * DD + d];
        red[d] = v * v;
        __syncthreads();
        for (int s2 = 64; s2 > 0; s2 >>= 1) {
            if (d < s2) red[d] += red[d + s2];
            __syncthreads();
        }
        float nrm = __fsqrt_rn(red[0]);
        __syncthreads();
        float val = 0.5f * __fdiv_rn(v, fmaxf(nrm, 1e-12f));
        __half hi = __float2half_rn(val);
        float rr  = val - __half2float(hi);
        __half lo = __float2half_rn(rr * 2048.0f);
        dhi[(size_t)r * KDIM + c * DD + d] = hi;
        dlo[(size_t)r * KDIM + c * DD + d] = lo;
    }
}

// ---------------- K3: 3-pass FP16 split GEMM  S = A(4096x512) * B(4096x512)^T ----------------
__global__ void __launch_bounds__(GT, 1) k_gemm() {
    extern __shared__ __align__(128) __half smh[];
    uint32_t sb;
    asm("{ .reg .u64 t; cvta.to.shared.u64 t, %1; cvt.u32.u64 %0, t; }"
        : "=r"(sb) : "l"(smh));
    const int tid = threadIdx.x;
    const int wid = tid >> 5, lane = tid & 31;
    const int g = lane >> 2, t = lane & 3;
    const int wm = wid >> 2, wn = wid & 3;
    const int bm = blockIdx.y * MT, bn = blockIdx.x * NT;

    float accH[2][4][4], accX[2][4][4];
#pragma unroll
    for (int mt = 0; mt < 2; mt++)
#pragma unroll
        for (int nt = 0; nt < 4; nt++)
#pragma unroll
            for (int r = 0; r < 4; r++) { accH[mt][nt][r] = 0.0f; accX[mt][nt][r] = 0.0f; }

    const int aRow = wm * 32 + (lane & 15);
    const int aK   = (lane >> 4) * 8;
    const uint32_t aOff0 = (uint32_t)((aRow)      * LDKH + aK) * 2;
    const uint32_t aOff1 = (uint32_t)((aRow + 16) * LDKH + aK) * 2;
    const int bRow = wn * 32 + (lane & 7) + ((lane >> 4) & 1) * 8;
    const int bK   = ((lane >> 3) & 1) * 8;
    const uint32_t bOff0 = (uint32_t)((bRow)      * LDKH + bK) * 2;
    const uint32_t bOff1 = (uint32_t)((bRow + 16) * LDKH + bK) * 2;

    auto load_chunk = [&](int kt, int stage) {
        uint32_t base = sb + (uint32_t)stage * (STAGE_H * 2);
        int row = tid >> 2, seg = tid & 3;
        uint32_t so = (uint32_t)(row * (LDKH * 2) + seg * 16);
        size_t goA = (size_t)(bm + row) * KDIM + kt * KCH + seg * 8;
        size_t goB = (size_t)(bn + row) * KDIM + kt * KCH + seg * 8;
        cpa16(base + so,                   g_Ahi + goA);
        cpa16(base + PLANE_H * 2     + so, g_Alo + goA);
        cpa16(base + PLANE_H * 4     + so, g_Bhi + goB);
        cpa16(base + PLANE_H * 6     + so, g_Blo + goB);
        asm volatile("cp.async.commit_group;" ::: "memory");
    };

    load_chunk(0, 0);
    load_chunk(1, 1);
    load_chunk(2, 2);

    for (int kt = 0; kt < NCHUNK; kt++) {
        if (kt <= 13)      asm volatile("cp.async.wait_group 2;" ::: "memory");
        else if (kt == 14) asm volatile("cp.async.wait_group 1;" ::: "memory");
        else               asm volatile("cp.async.wait_group 0;" ::: "memory");
        __syncthreads();

        if (kt + 3 < NCHUNK) load_chunk(kt + 3, (kt + 3) & (NSTAGE - 1));

        uint32_t stg = sb + (uint32_t)(kt & (NSTAGE - 1)) * (STAGE_H * 2);

#pragma unroll
        for (int ks = 0; ks < 2; ks++) {
            const uint32_t kboff = (uint32_t)ks * 32;
            uint32_t bh[4][2], bl[4][2];
            ldsm4(bh[0][0], bh[0][1], bh[1][0], bh[1][1], stg + PLANE_H * 4 + bOff0 + kboff);
            ldsm4(bh[2][0], bh[2][1], bh[3][0], bh[3][1], stg + PLANE_H * 4 + bOff1 + kboff);
            ldsm4(bl[0][0], bl[0][1], bl[1][0], bl[1][1], stg + PLANE_H * 6 + bOff0 + kboff);
            ldsm4(bl[2][0], bl[2][1], bl[3][0], bl[3][1], stg + PLANE_H * 6 + bOff1 + kboff);
#pragma unroll
            for (int mt = 0; mt < 2; mt++) {
                uint32_t aoff = (mt == 0) ? aOff0 : aOff1;
                uint32_t ah0, ah1, ah2, ah3, al0, al1, al2, al3;
                ldsm4(ah0, ah1, ah2, ah3, stg +               aoff + kboff);
                ldsm4(al0, al1, al2, al3, stg + PLANE_H * 2 + aoff + kboff);
#pragma unroll
                for (int nt = 0; nt < 4; nt++) {
                    mma16(accH[mt][nt], ah0, ah1, ah2, ah3, bh[nt][0], bh[nt][1]);
                    mma16(accX[mt][nt], ah0, ah1, ah2, ah3, bl[nt][0], bl[nt][1]);
                    mma16(accX[mt][nt], al0, al1, al2, al3, bh[nt][0], bh[nt][1]);
                }
            }
        }
    }

    __syncthreads();
    const float IS = 1.0f / 2048.0f;
#pragma unroll
    for (int mt = 0; mt < 2; mt++) {
        int r0 = bm + wm * 32 + mt * 16 + g;
#pragma unroll
        for (int nt = 0; nt < 4; nt++) {
            int c = bn + wn * 32 + nt * 8 + 2 * t;
            float v0 = fmaf(accX[mt][nt][0], IS, accH[mt][nt][0]);
            float v1 = fmaf(accX[mt][nt][1], IS, accH[mt][nt][1]);
            float v2 = fmaf(accX[mt][nt][2], IS, accH[mt][nt][2]);
            float v3 = fmaf(accX[mt][nt][3], IS, accH[mt][nt][3]);
            *(float2*)(g_S + (size_t)r0 * MMm + c)       = make_float2(v0, v1);
            *(float2*)(g_S + (size_t)(r0 + 8) * MMm + c) = make_float2(v2, v3);
        }
    }
}

// ---------------- K4: mask existing incidences (dedup-safe) ----------------
__global__ void k_mask(const int* __restrict__ V, const int* __restrict__ E) {
    int i = blockIdx.x * blockDim.x + threadIdx.x;
    if (i < NNZ) {
        atomicExch(&g_S[(size_t)V[i] * MMm + E[i]], -1e30f);
    }
}

// ---------------- K5: top-11-bit histogram (positive values only) ----------------
__global__ void k_hist() {
    __shared__ unsigned h[2048];
    for (int j = threadIdx.x; j < 2048; j += blockDim.x) h[j] = 0;
    __syncthreads();
    int i  = blockIdx.x * blockDim.x + threadIdx.x;
    int st = gridDim.x * blockDim.x;
    const float4* S4 = (const float4*)g_S;
    for (int j = i; j < NM / 4; j += st) {
        float4 s = S4[j];
        if (s.x > 0.0f) atomicAdd(&h[f2ord(s.x) >> 21], 1u);
        if (s.y > 0.0f) atomicAdd(&h[f2ord(s.y) >> 21], 1u);
        if (s.z > 0.0f) atomicAdd(&h[f2ord(s.z) >> 21], 1u);
        if (s.w > 0.0f) atomicAdd(&h[f2ord(s.w) >> 21], 1u);
    }
    __syncthreads();
    for (int j = threadIdx.x; j < 2048; j += blockDim.x)
        if (h[j]) atomicAdd(&g_hist[j], h[j]);
}

// ---------------- K6: find threshold bucket B1 (1 block, 1024 thr) ----------------
__global__ void k_pick() {
    __shared__ unsigned c[2048];
    int t = threadIdx.x;
    c[t] = g_hist[t];
    c[t + 1024] = g_hist[t + 1024];
    __syncthreads();
    for (int off = 1; off < 2048; off <<= 1) {
        unsigned a0 = (t + off < 2048) ? c[t + off] : 0u;
        unsigned a1 = (t + 1024 + off < 2048) ? c[t + 1024 + off] : 0u;
        __syncthreads();
        c[t] += a0; c[t + 1024] += a1;
        __syncthreads();
    }
    for (int b = t; b < 2048; b += 1024) {
        unsigned cum = c[b], nxt = (b + 1 < 2048) ? c[b + 1] : 0u;
        if (cum >= (unsigned)KADD && nxt < (unsigned)KADD) {
            g_B1 = (unsigned)b;
        }
    }
}

// ---------------- K7: collect (value, index) for all buckets >= B1 ----------------
__global__ void k_collect() {
    unsigned B1 = g_B1;
    int lane = threadIdx.x & 31;
    int i  = blockIdx.x * blockDim.x + threadIdx.x;
    int st = gridDim.x * blockDim.x;
    const float4* S4 = (const float4*)g_S;
    // NM/4 is an exact multiple of st: uniform trip count -> warp-sync ballots safe
    for (int j = i; j < NM / 4; j += st) {
        float4 s = S4[j];
        unsigned u[4] = { f2ord(s.x), f2ord(s.y), f2ord(s.z), f2ord(s.w) };
#pragma unroll
        for (int q = 0; q < 4; q++) {
            bool pred = (u[q] >> 21) >= B1;
            unsigned m = __ballot_sync(0xFFFFFFFFu, pred);
            if (m) {
                int leader = __ffs(m) - 1;
                unsigned base = 0;
                if (lane == leader) base = atomicAdd(&g_candCount, (unsigned)__popc(m));
                base = __shfl_sync(0xFFFFFFFFu, base, leader);
                unsigned rank = __popc(m & ((1u << lane) - 1u));
                unsigned pos = base + rank;
                if (pred && pos < CAPC) {
                    g_cand[pos] = u[q];
                    g_cidx[pos] = (unsigned)j * 4u + (unsigned)q;
                }
            }
        }
    }
}

// ---------------- K8: exact rank-KADD via 11+11+10 bit refine over candidates ----------------
__global__ void k_select() {
    __shared__ unsigned h[2048];
    __shared__ unsigned sB1, sr1, sb2, sr2;
    int t = threadIdx.x;  // 1024
    unsigned nc = g_candCount; if (nc > CAPC) nc = CAPC;

    // level 1: top-11 bits
    h[t] = 0; h[t + 1024] = 0;
    __syncthreads();
    for (unsigned i = t; i < nc; i += 1024)
        atomicAdd(&h[g_cand[i] >> 21], 1u);
    __syncthreads();
    for (int off = 1; off < 2048; off <<= 1) {
        unsigned a0 = (t + off < 2048) ? h[t + off] : 0u;
        unsigned a1 = (t + 1024 + off < 2048) ? h[t + 1024 + off] : 0u;
        __syncthreads();
        h[t] += a0; h[t + 1024] += a1;
        __syncthreads();
    }
    for (int b = t; b < 2048; b += 1024) {
        unsigned cum = h[b], nxt = (b + 1 < 2048) ? h[b + 1] : 0u;
        if (cum >= (unsigned)KADD && nxt < (unsigned)KADD) { sB1 = (unsigned)b; sr1 = (unsigned)KADD - nxt; }
    }
    __syncthreads();
    unsigned B1 = sB1, r1 = sr1;

    // level 2: middle-11 bits within B1
    h[t] = 0; h[t + 1024] = 0;
    __syncthreads();
    for (unsigned i = t; i < nc; i += 1024) {
        unsigned u = g_cand[i];
        if ((u >> 21) == B1) atomicAdd(&h[(u >> 10) & 2047u], 1u);
    }
    __syncthreads();
    for (int off = 1; off < 2048; off <<= 1) {
        unsigned a0 = (t + off < 2048) ? h[t + off] : 0u;
        unsigned a1 = (t + 1024 + off < 2048) ? h[t + 1024 + off] : 0u;
        __syncthreads();
        h[t] += a0; h[t + 1024] += a1;
        __syncthreads();
    }
    for (int b = t; b < 2048; b += 1024) {
        unsigned cum = h[b], nxt = (b + 1 < 2048) ? h[b + 1] : 0u;
        if (cum >= r1 && nxt < r1) { sb2 = (unsigned)b; sr2 = r1 - nxt; }
    }
    __syncthreads();
    unsigned b2 = sb2, r2 = sr2;
    unsigned top21 = (B1 << 11) | b2;

    // level 3: low-10 bits within (B1,b2)
    h[t] = 0;
    __syncthreads();
    for (unsigned i = t; i < nc; i += 1024) {
        unsigned u = g_cand[i];
        if ((u >> 10) == top21) atomicAdd(&h[u & 1023u], 1u);
    }
    __syncthreads();
    for (int off = 1; off < 1024; off <<= 1) {
        unsigned a = (t + off < 1024) ? h[t + off] : 0u;
        __syncthreads();
        h[t] += a;
        __syncthreads();
    }
    unsigned cum = h[t], nxt = (t + 1 < 1024) ? h[t + 1] : 0u;
    if (cum >= r2 && nxt < r2)
        g_Tbits = (B1 << 21) | (b2 << 10) | (unsigned)t;
}

// ---------------- K9a: scatter existing incidences: out[v,e] = mask ? 1 : 0 ----------------
__global__ void k_hfin(const int* __restrict__ V, const int* __restrict__ E,
                       const float* __restrict__ P, const float* __restrict__ Eps,
                       float* __restrict__ out) {
    int i = blockIdx.x * blockDim.x + threadIdx.x;
    if (i < NNZ) {
        size_t idx = (size_t)V[i] * MMm + E[i];
        if (hardmask(P[idx], Eps[idx])) out[idx] = 1.0f;
    }
}

// ---------------- K9b: scatter top-KADD cells: out[idx] = mask ? 1 : 0 ----------------
__global__ void k_sfin(const float* __restrict__ P, const float* __restrict__ Eps,
                       float* __restrict__ out) {
    unsigned nc = g_candCount; if (nc > CAPC) nc = CAPC;
    unsigned T = g_Tbits;
    unsigned i  = blockIdx.x * blockDim.x + threadIdx.x;
    unsigned st = gridDim.x * blockDim.x;
    for (unsigned k = i; k < nc; k += st) {
        if (g_cand[k] >= T) {
            size_t idx = (size_t)g_cidx[k];
            if (hardmask(P[idx], Eps[idx])) out[idx] = 1.0f;
        }
    }
}

// ---------------- launch ----------------
extern "C" void kernel_launch(void* const* d_in, const int* in_sizes, int n_in,
                              void* d_out, int out_size) {
    const float* X   = (const float*)d_in[0];
    const int*   V   = (const int*)d_in[2];
    const int*   E   = (const int*)d_in[3];
    const float* P   = (const float*)d_in[4];
    const float* W   = (const float*)d_in[5];
    const float* Eps = (const float*)d_in[6];
    float* out = (float*)d_out;

    cudaFuncSetAttribute(k_gemm, cudaFuncAttributeMaxDynamicSharedMemorySize, SMEM_BYTES);

    k_zero<<<64, 256>>>();
    k_zout<<<NM / 4 / 256, 256>>>(out);
    k_count<<<NNZ / 256, 256>>>(E);
    k_prefix<<<1, 1024>>>();
    k_fill<<<NNZ / 256, 256>>>(V, E);
    {
        dim3 fg(NN, 2);
        k_feat<<<fg, 128>>>(X, W);
    }
    {
        dim3 gg(MMm / NT, NN / MT);   // (32, 32)
        k_gemm<<<gg, GT, SMEM_BYTES>>>();
    }
    k_mask<<<NNZ / 256, 256>>>(V, E);
    k_hist<<<2048, 256>>>();
    k_pick<<<1, 1024>>>();
    k_collect<<<2048, 256>>>();
    k_select<<<1, 1024>>>();
    k_hfin<<<NNZ / 256, 256>>>(V, E, P, Eps, out);
    k_sfin<<<512, 256>>>(P, Eps, out);
}